// round 2
// baseline (speedup 1.0000x reference)
#include <cuda_runtime.h>
#include <math.h>

#define BATCH 8
#define CCH 192
#define HEADS 16
#define HD 12
#define HW 16384
#define NSPLIT 32
#define KCHUNK 512   // HW / NSPLIT

// ---------------- scratch (device globals; no allocation) ----------------
__device__ float g_Spart[BATCH * NSPLIT * CCH * CCH];   // 37.7 MB split-K partials
__device__ float g_S[BATCH * CCH * CCH];                // X X^T per batch
__device__ float g_Meff[BATCH * CCH * CCH];             // folded attn*Wv per batch
__device__ float g_Y[(size_t)BATCH * CCH * HW];         // attention output (pre-dwconv)
__device__ float g_Z[(size_t)BATCH * CCH * HW];         // dwconv output

// ---------------- kernel 1: S partials = X X^T over a K-chunk ----------------
// grid: (9 = 3x3 m/n tiles, NSPLIT, BATCH), block 256. 64x64 tile, 4x4 per thread.
__global__ void s_partial_kernel(const float* __restrict__ x) {
    const int tm = blockIdx.x / 3, tn = blockIdx.x % 3;
    const int ks = blockIdx.y, b = blockIdx.z;
    const float* Xb = x + (size_t)b * CCH * HW;
    const int p0 = ks * KCHUNK;

    __shared__ float As[16][68];
    __shared__ float Bs[16][68];

    const int t  = threadIdx.x;
    const int tx = t & 15, ty = t >> 4;
    const int lr = t >> 2, lc = (t & 3) * 4;  // 64 rows x 16 k per stage

    float acc[4][4] = {};

    for (int kk0 = 0; kk0 < KCHUNK; kk0 += 16) {
        float4 av = *(const float4*)(Xb + (size_t)(tm * 64 + lr) * HW + p0 + kk0 + lc);
        float4 bv = *(const float4*)(Xb + (size_t)(tn * 64 + lr) * HW + p0 + kk0 + lc);
        As[lc + 0][lr] = av.x; As[lc + 1][lr] = av.y; As[lc + 2][lr] = av.z; As[lc + 3][lr] = av.w;
        Bs[lc + 0][lr] = bv.x; Bs[lc + 1][lr] = bv.y; Bs[lc + 2][lr] = bv.z; Bs[lc + 3][lr] = bv.w;
        __syncthreads();
#pragma unroll
        for (int kk = 0; kk < 16; kk++) {
            float a[4], bb[4];
#pragma unroll
            for (int i = 0; i < 4; i++) a[i] = As[kk][ty * 4 + i];
#pragma unroll
            for (int j = 0; j < 4; j++) bb[j] = Bs[kk][tx * 4 + j];
#pragma unroll
            for (int i = 0; i < 4; i++)
#pragma unroll
                for (int j = 0; j < 4; j++) acc[i][j] += a[i] * bb[j];
        }
        __syncthreads();
    }

    float* sp = g_Spart + (size_t)(b * NSPLIT + ks) * CCH * CCH;
#pragma unroll
    for (int i = 0; i < 4; i++) {
        float4 v = make_float4(acc[i][0], acc[i][1], acc[i][2], acc[i][3]);
        *(float4*)(sp + (size_t)(tm * 64 + ty * 4 + i) * CCH + tn * 64 + tx * 4) = v;
    }
}

// ---------------- kernel 2: reduce split-K partials ----------------
__global__ void s_reduce_kernel() {
    int gid = blockIdx.x * blockDim.x + threadIdx.x;
    if (gid >= BATCH * CCH * CCH) return;
    int b = gid / (CCH * CCH), mn = gid % (CCH * CCH);
    float s = 0.f;
#pragma unroll 8
    for (int ks = 0; ks < NSPLIT; ks++)
        s += g_Spart[(size_t)(b * NSPLIT + ks) * CCH * CCH + mn];
    g_S[gid] = s;
}

// ---------------- kernel 3: per-(b,h) attention -> Meff ----------------
// G = Wq S Wk^T, qnorm^2 = diag(Wq S Wq^T), knorm^2 = diag(Wk S Wk^T),
// attn = softmax(G * temp / (qn kn)), Meff rows = attn @ Wv.
// grid (HEADS, BATCH), 192 threads. Smem strides padded to 196 to kill 32-way conflicts.
__global__ void attn_build_kernel(const float* __restrict__ w_qkv,
                                  const float* __restrict__ temperature) {
    const int h = blockIdx.x, b = blockIdx.y, t = threadIdx.x;

    __shared__ float sWq[HD][196];
    __shared__ float sWk[HD][196];
    __shared__ float sT[2 * HD][196];   // reused for Wv later
    __shared__ float sG[HD][HD];
    __shared__ float sAttn[HD][HD];
    __shared__ float sQn[HD], sKn[HD];

    for (int i = t; i < HD * CCH; i += 192) {
        int c = i / CCH, j = i % CCH;
        sWq[c][j] = w_qkv[(h * HD + c) * CCH + j];
        sWk[c][j] = w_qkv[(CCH + h * HD + c) * CCH + j];
    }
    __syncthreads();

    // T = [Wq;Wk] * S   (thread t owns column t)
    {
        float tq[HD] = {}, tk[HD] = {};
        const float* Sb = g_S + b * CCH * CCH;
        for (int m = 0; m < CCH; m++) {
            float s = Sb[m * CCH + t];
#pragma unroll
            for (int c = 0; c < HD; c++) { tq[c] += sWq[c][m] * s; tk[c] += sWk[c][m] * s; }
        }
#pragma unroll
        for (int c = 0; c < HD; c++) { sT[c][t] = tq[c]; sT[HD + c][t] = tk[c]; }
    }
    __syncthreads();

    // G and diagonal norms (168 tasks over 192 threads)
    if (t < 144) {
        int c = t / HD, d = t % HD;
        float s = 0.f;
        for (int j = 0; j < CCH; j++) s += sT[c][j] * sWk[d][j];
        sG[c][d] = s;
    } else if (t < 156) {
        int c = t - 144; float s = 0.f;
        for (int j = 0; j < CCH; j++) s += sT[c][j] * sWq[c][j];
        sQn[c] = s;
    } else if (t < 168) {
        int c = t - 156; float s = 0.f;
        for (int j = 0; j < CCH; j++) s += sT[HD + c][j] * sWk[c][j];
        sKn[c] = s;
    }
    __syncthreads();

    // softmax rows (threads 0..11) -- sT no longer needed, so all threads also load Wv
    if (t < HD) {
        float temp = temperature[h];
        float qn = fmaxf(sqrtf(fmaxf(sQn[t], 0.f)), 1e-12f);
        float lg[HD];
        float mx = -1e30f;
#pragma unroll
        for (int d = 0; d < HD; d++) {
            float kn = fmaxf(sqrtf(fmaxf(sKn[d], 0.f)), 1e-12f);
            lg[d] = sG[t][d] * temp / (qn * kn);
            mx = fmaxf(mx, lg[d]);
        }
        float sum = 0.f;
#pragma unroll
        for (int d = 0; d < HD; d++) { lg[d] = expf(lg[d] - mx); sum += lg[d]; }
        float inv = 1.f / sum;
#pragma unroll
        for (int d = 0; d < HD; d++) sAttn[t][d] = lg[d] * inv;
    }
    float (*sWv)[196] = sT;  // reuse
    for (int i = t; i < HD * CCH; i += 192) {
        int c = i / CCH, j = i % CCH;
        sWv[c][j] = w_qkv[(2 * CCH + h * HD + c) * CCH + j];
    }
    __syncthreads();

    // Meff rows for this head: Meff[h*12+c][j] = sum_d attn[c][d] * Wv[d][j]
#pragma unroll
    for (int c = 0; c < HD; c++) {
        float s = 0.f;
#pragma unroll
        for (int d = 0; d < HD; d++) s += sAttn[c][d] * sWv[d][t];
        g_Meff[(size_t)(b * CCH + h * HD + c) * CCH + t] = s;
    }
}

// ---------------- kernel 4: C[b] = A_b[192,192] @ B[b][192,HW] ----------------
// Used for Y = Meff @ X and out = Wproj @ Z (aStride=0 shares A across batches).
// grid (HW/64, 3, BATCH), block 256, 64x64 tile, 4x4 per thread, BK=16.
__global__ void gemm192_kernel(const float* __restrict__ A, int aStride,
                               const float* __restrict__ B, float* __restrict__ Cout) {
    const float* Ab = A + (size_t)blockIdx.z * aStride;
    const float* Bb = B + (size_t)blockIdx.z * CCH * HW;
    float* Cb = Cout + (size_t)blockIdx.z * CCH * HW;
    const int m0 = blockIdx.y * 64, n0 = blockIdx.x * 64;

    __shared__ float As[16][68];
    __shared__ float Bs[16][68];

    const int t  = threadIdx.x;
    const int tx = t & 15, ty = t >> 4;
    const int lr = t >> 2, lc = (t & 3) * 4;    // A: 64 rows x 16 k
    const int br = t >> 4, bc = (t & 15) * 4;   // B: 16 rows x 64 p

    float acc[4][4] = {};

    for (int k0 = 0; k0 < CCH; k0 += 16) {
        float4 av = *(const float4*)(Ab + (m0 + lr) * CCH + k0 + lc);
        As[lc + 0][lr] = av.x; As[lc + 1][lr] = av.y; As[lc + 2][lr] = av.z; As[lc + 3][lr] = av.w;
        float4 bv = *(const float4*)(Bb + (size_t)(k0 + br) * HW + n0 + bc);
        *(float4*)&Bs[br][bc] = bv;
        __syncthreads();
#pragma unroll
        for (int kk = 0; kk < 16; kk++) {
            float a[4], bb[4];
#pragma unroll
            for (int i = 0; i < 4; i++) a[i] = As[kk][ty * 4 + i];
#pragma unroll
            for (int j = 0; j < 4; j++) bb[j] = Bs[kk][tx * 4 + j];
#pragma unroll
            for (int i = 0; i < 4; i++)
#pragma unroll
                for (int j = 0; j < 4; j++) acc[i][j] += a[i] * bb[j];
        }
        __syncthreads();
    }
#pragma unroll
    for (int i = 0; i < 4; i++) {
        float4 v = make_float4(acc[i][0], acc[i][1], acc[i][2], acc[i][3]);
        *(float4*)(Cb + (size_t)(m0 + ty * 4 + i) * HW + n0 + tx * 4) = v;
    }
}

// ---------------- kernel 5: depthwise 3x3, pad 1 ----------------
// grid (4, 16, BATCH*CCH), block 256 = 32x8 pixels.
__global__ void dwconv_kernel(const float* __restrict__ wdw) {
    const int bc = blockIdx.z;
    const int c = bc % CCH;
    const int xx = blockIdx.x * 32 + (threadIdx.x & 31);
    const int yy = blockIdx.y * 8 + (threadIdx.x >> 5);
    const float* Yc = g_Y + (size_t)bc * HW;

    float w[9];
#pragma unroll
    for (int i = 0; i < 9; i++) w[i] = wdw[c * 9 + i];

    float acc = 0.f;
#pragma unroll
    for (int ky = 0; ky < 3; ky++) {
        int sy = yy + ky - 1;
        if (sy < 0 || sy >= 128) continue;
#pragma unroll
        for (int kx = 0; kx < 3; kx++) {
            int sx = xx + kx - 1;
            if (sx < 0 || sx >= 128) continue;
            acc += w[ky * 3 + kx] * __ldg(Yc + sy * 128 + sx);
        }
    }
    g_Z[(size_t)bc * HW + yy * 128 + xx] = acc;
}

// ---------------- launch ----------------
extern "C" void kernel_launch(void* const* d_in, const int* in_sizes, int n_in,
                              void* d_out, int out_size) {
    const float* x           = (const float*)d_in[0];
    const float* w_qkv       = (const float*)d_in[1];
    const float* w_dw        = (const float*)d_in[2];
    const float* w_proj      = (const float*)d_in[3];
    const float* temperature = (const float*)d_in[4];
    float* out = (float*)d_out;

    float *pMeff, *pY, *pZ;
    cudaGetSymbolAddress((void**)&pMeff, g_Meff);
    cudaGetSymbolAddress((void**)&pY, g_Y);
    cudaGetSymbolAddress((void**)&pZ, g_Z);

    // 1) S = X X^T (split-K partials + deterministic reduce)
    s_partial_kernel<<<dim3(9, NSPLIT, BATCH), 256>>>(x);
    s_reduce_kernel<<<(BATCH * CCH * CCH + 255) / 256, 256>>>();

    // 2) tiny: G, norms, softmax, Meff
    attn_build_kernel<<<dim3(HEADS, BATCH), 192>>>(w_qkv, temperature);

    // 3) Y = Meff @ X   (attention output, [b,192,HW])
    gemm192_kernel<<<dim3(HW / 64, 3, BATCH), 256>>>(pMeff, CCH * CCH, x, pY);

    // 4) depthwise 3x3
    dwconv_kernel<<<dim3(4, 16, BATCH * CCH), 256>>>(w_dw);

    // 5) out = Wproj @ Z
    gemm192_kernel<<<dim3(HW / 64, 3, BATCH), 256>>>(w_proj, 0, pZ, out);
}

// round 3
// speedup vs baseline: 1.1380x; 1.1380x over previous
#include <cuda_runtime.h>
#include <math.h>

#define BATCH 8
#define CCH 192
#define HEADS 16
#define HD 12
#define HW 16384
#define NSPLIT 32
#define KCHUNK 512   // HW / NSPLIT

// ---------------- scratch (device globals; no allocation) ----------------
__device__ float g_Spart[BATCH * NSPLIT * CCH * CCH];   // split-K partials (upper tiles only)
__device__ float g_S[BATCH * CCH * CCH];                // X X^T per batch
__device__ float g_Meff[BATCH * CCH * CCH];             // folded attn*Wv per batch
__device__ float g_Y[(size_t)BATCH * CCH * HW];         // attention output (pre-dwconv)
__device__ float g_Z[(size_t)BATCH * CCH * HW];         // dwconv output

// upper-triangular 64x64 tile pairs of the 3x3 tile grid
__constant__ int c_tm[6] = {0, 0, 0, 1, 1, 2};
__constant__ int c_tn[6] = {0, 1, 2, 1, 2, 2};

// ---------------- kernel 1: S partials = X X^T over a K-chunk ----------------
// grid (6, NSPLIT, BATCH), 128 threads. 64x64 tile, 8x4 microtile, double-buffered.
__global__ void s_partial_kernel(const float* __restrict__ x) {
    const int tm = c_tm[blockIdx.x], tn = c_tn[blockIdx.x];
    const int ks = blockIdx.y, b = blockIdx.z;
    const float* Xb = x + (size_t)b * CCH * HW;
    const int p0 = ks * KCHUNK;

    __shared__ float As[2][16][68];
    __shared__ float Bs[2][16][68];

    const int t  = threadIdx.x;
    const int tx = t & 15, ty = t >> 4;          // compute: 16 n-groups x 8 m-groups
    const int a_r = t & 63, a_k = (t >> 6) * 8;  // load: 64 rows x 2 k-halves

    const float* Arow = Xb + (size_t)(tm * 64 + a_r) * HW + p0 + a_k;
    const float* Brow = Xb + (size_t)(tn * 64 + a_r) * HW + p0 + a_k;

    float acc[8][4] = {};

    // preload first k-block
    float4 av0 = *(const float4*)(Arow);
    float4 av1 = *(const float4*)(Arow + 4);
    float4 bv0 = *(const float4*)(Brow);
    float4 bv1 = *(const float4*)(Brow + 4);
    As[0][a_k + 0][a_r] = av0.x; As[0][a_k + 1][a_r] = av0.y; As[0][a_k + 2][a_r] = av0.z; As[0][a_k + 3][a_r] = av0.w;
    As[0][a_k + 4][a_r] = av1.x; As[0][a_k + 5][a_r] = av1.y; As[0][a_k + 6][a_r] = av1.z; As[0][a_k + 7][a_r] = av1.w;
    Bs[0][a_k + 0][a_r] = bv0.x; Bs[0][a_k + 1][a_r] = bv0.y; Bs[0][a_k + 2][a_r] = bv0.z; Bs[0][a_k + 3][a_r] = bv0.w;
    Bs[0][a_k + 4][a_r] = bv1.x; Bs[0][a_k + 5][a_r] = bv1.y; Bs[0][a_k + 6][a_r] = bv1.z; Bs[0][a_k + 7][a_r] = bv1.w;
    __syncthreads();

    int buf = 0;
    const int NIT = KCHUNK / 16;
    for (int it = 0; it < NIT; it++) {
        float4 nav0, nav1, nbv0, nbv1;
        if (it < NIT - 1) {
            const float* Ap = Arow + (it + 1) * 16;
            const float* Bp = Brow + (it + 1) * 16;
            nav0 = *(const float4*)(Ap);     nav1 = *(const float4*)(Ap + 4);
            nbv0 = *(const float4*)(Bp);     nbv1 = *(const float4*)(Bp + 4);
        }
#pragma unroll
        for (int kk = 0; kk < 16; kk++) {
            float a[8], bb[4];
            *(float4*)(a)     = *(const float4*)&As[buf][kk][ty * 8];
            *(float4*)(a + 4) = *(const float4*)&As[buf][kk][ty * 8 + 4];
            *(float4*)(bb)    = *(const float4*)&Bs[buf][kk][tx * 4];
#pragma unroll
            for (int i = 0; i < 8; i++)
#pragma unroll
                for (int j = 0; j < 4; j++) acc[i][j] += a[i] * bb[j];
        }
        if (it < NIT - 1) {
            int nb = buf ^ 1;
            As[nb][a_k + 0][a_r] = nav0.x; As[nb][a_k + 1][a_r] = nav0.y; As[nb][a_k + 2][a_r] = nav0.z; As[nb][a_k + 3][a_r] = nav0.w;
            As[nb][a_k + 4][a_r] = nav1.x; As[nb][a_k + 5][a_r] = nav1.y; As[nb][a_k + 6][a_r] = nav1.z; As[nb][a_k + 7][a_r] = nav1.w;
            Bs[nb][a_k + 0][a_r] = nbv0.x; Bs[nb][a_k + 1][a_r] = nbv0.y; Bs[nb][a_k + 2][a_r] = nbv0.z; Bs[nb][a_k + 3][a_r] = nbv0.w;
            Bs[nb][a_k + 4][a_r] = nbv1.x; Bs[nb][a_k + 5][a_r] = nbv1.y; Bs[nb][a_k + 6][a_r] = nbv1.z; Bs[nb][a_k + 7][a_r] = nbv1.w;
            __syncthreads();
            buf = nb;
        }
    }

    float* sp = g_Spart + (size_t)(b * NSPLIT + ks) * CCH * CCH;
#pragma unroll
    for (int i = 0; i < 8; i++) {
        float4 v = make_float4(acc[i][0], acc[i][1], acc[i][2], acc[i][3]);
        *(float4*)(sp + (size_t)(tm * 64 + ty * 8 + i) * CCH + tn * 64 + tx * 4) = v;
    }
}

// ---------------- kernel 2: reduce split-K partials (mirror lower triangle) --
__global__ void s_reduce_kernel() {
    int gid = blockIdx.x * blockDim.x + threadIdx.x;
    if (gid >= BATCH * CCH * CCH) return;
    int b = gid / (CCH * CCH), mn = gid % (CCH * CCH);
    int m = mn / CCH, n = mn % CCH;
    int off = ((m >> 6) <= (n >> 6)) ? (m * CCH + n) : (n * CCH + m);
    const float* base = g_Spart + (size_t)b * NSPLIT * CCH * CCH;
    float s = 0.f;
#pragma unroll 8
    for (int ks = 0; ks < NSPLIT; ks++)
        s += base[(size_t)ks * CCH * CCH + off];
    g_S[gid] = s;
}

// ---------------- kernel 3: per-(b,h) attention -> Meff ----------------
__global__ void attn_build_kernel(const float* __restrict__ w_qkv,
                                  const float* __restrict__ temperature) {
    const int h = blockIdx.x, b = blockIdx.y, t = threadIdx.x;

    __shared__ float sWq[HD][196];
    __shared__ float sWk[HD][196];
    __shared__ float sT[2 * HD][196];   // reused for Wv later
    __shared__ float sG[HD][HD];
    __shared__ float sAttn[HD][HD];
    __shared__ float sQn[HD], sKn[HD];

    for (int i = t; i < HD * CCH; i += 192) {
        int c = i / CCH, j = i % CCH;
        sWq[c][j] = w_qkv[(h * HD + c) * CCH + j];
        sWk[c][j] = w_qkv[(CCH + h * HD + c) * CCH + j];
    }
    __syncthreads();

    // T = [Wq;Wk] * S   (thread t owns column t)
    {
        float tq[HD] = {}, tk[HD] = {};
        const float* Sb = g_S + b * CCH * CCH;
        for (int m = 0; m < CCH; m++) {
            float s = Sb[m * CCH + t];
#pragma unroll
            for (int c = 0; c < HD; c++) { tq[c] += sWq[c][m] * s; tk[c] += sWk[c][m] * s; }
        }
#pragma unroll
        for (int c = 0; c < HD; c++) { sT[c][t] = tq[c]; sT[HD + c][t] = tk[c]; }
    }
    __syncthreads();

    // G and diagonal norms
    if (t < 144) {
        int c = t / HD, d = t % HD;
        float s = 0.f;
        for (int j = 0; j < CCH; j++) s += sT[c][j] * sWk[d][j];
        sG[c][d] = s;
    } else if (t < 156) {
        int c = t - 144; float s = 0.f;
        for (int j = 0; j < CCH; j++) s += sT[c][j] * sWq[c][j];
        sQn[c] = s;
    } else if (t < 168) {
        int c = t - 156; float s = 0.f;
        for (int j = 0; j < CCH; j++) s += sT[HD + c][j] * sWk[c][j];
        sKn[c] = s;
    }
    __syncthreads();

    if (t < HD) {
        float temp = temperature[h];
        float qn = fmaxf(sqrtf(fmaxf(sQn[t], 0.f)), 1e-12f);
        float lg[HD];
        float mx = -1e30f;
#pragma unroll
        for (int d = 0; d < HD; d++) {
            float kn = fmaxf(sqrtf(fmaxf(sKn[d], 0.f)), 1e-12f);
            lg[d] = sG[t][d] * temp / (qn * kn);
            mx = fmaxf(mx, lg[d]);
        }
        float sum = 0.f;
#pragma unroll
        for (int d = 0; d < HD; d++) { lg[d] = expf(lg[d] - mx); sum += lg[d]; }
        float inv = 1.f / sum;
#pragma unroll
        for (int d = 0; d < HD; d++) sAttn[t][d] = lg[d] * inv;
    }
    float (*sWv)[196] = sT;  // reuse
    for (int i = t; i < HD * CCH; i += 192) {
        int c = i / CCH, j = i % CCH;
        sWv[c][j] = w_qkv[(2 * CCH + h * HD + c) * CCH + j];
    }
    __syncthreads();

#pragma unroll
    for (int c = 0; c < HD; c++) {
        float s = 0.f;
#pragma unroll
        for (int d = 0; d < HD; d++) s += sAttn[c][d] * sWv[d][t];
        g_Meff[(size_t)(b * CCH + h * HD + c) * CCH + t] = s;
    }
}

// ---------------- kernel 4: C[b] = A_b[192,192] @ B[b][192,HW] ----------------
// 64x128 tile, 128 threads, 8x8 microtile, double-buffered smem.
// grid (HW/128, 3, BATCH).
__global__ void gemm192_kernel(const float* __restrict__ A, int aStride,
                               const float* __restrict__ B, float* __restrict__ Cout) {
    const float* Ab = A + (size_t)blockIdx.z * aStride;
    const float* Bb = B + (size_t)blockIdx.z * CCH * HW;
    float* Cb = Cout + (size_t)blockIdx.z * CCH * HW;
    const int m0 = blockIdx.y * 64, n0 = blockIdx.x * 128;

    __shared__ float As[2][16][68];
    __shared__ float Bs[2][16][136];

    const int t  = threadIdx.x;
    const int tx = t & 15, ty = t >> 4;          // compute: 16 n-groups(8) x 8 m-groups(8)
    const int a_r = t & 63, a_k = (t >> 6) * 8;  // A load: 64 rows x 2 k-halves
    const int b_row = t >> 5, b_col = (t & 31) * 4;  // B load helper (f = t + i*128)

    float acc[8][8] = {};

    // preload k-block 0
    const float* Ap0 = Ab + (m0 + a_r) * CCH + a_k;
    float4 av0 = *(const float4*)(Ap0);
    float4 av1 = *(const float4*)(Ap0 + 4);
    float4 bv[4];
#pragma unroll
    for (int i = 0; i < 4; i++)
        bv[i] = *(const float4*)(Bb + (size_t)(b_row + i * 4) * HW + n0 + b_col);

    As[0][a_k + 0][a_r] = av0.x; As[0][a_k + 1][a_r] = av0.y; As[0][a_k + 2][a_r] = av0.z; As[0][a_k + 3][a_r] = av0.w;
    As[0][a_k + 4][a_r] = av1.x; As[0][a_k + 5][a_r] = av1.y; As[0][a_k + 6][a_r] = av1.z; As[0][a_k + 7][a_r] = av1.w;
#pragma unroll
    for (int i = 0; i < 4; i++)
        *(float4*)&Bs[0][b_row + i * 4][b_col] = bv[i];
    __syncthreads();

    int buf = 0;
    const int NIT = CCH / 16;   // 12
    for (int it = 0; it < NIT; it++) {
        float4 nav0, nav1, nbv[4];
        if (it < NIT - 1) {
            int k0 = (it + 1) * 16;
            const float* Ap = Ab + (m0 + a_r) * CCH + k0 + a_k;
            nav0 = *(const float4*)(Ap);
            nav1 = *(const float4*)(Ap + 4);
#pragma unroll
            for (int i = 0; i < 4; i++)
                nbv[i] = *(const float4*)(Bb + (size_t)(k0 + b_row + i * 4) * HW + n0 + b_col);
        }
#pragma unroll
        for (int kk = 0; kk < 16; kk++) {
            float a[8], bb[8];
            *(float4*)(a)      = *(const float4*)&As[buf][kk][ty * 8];
            *(float4*)(a + 4)  = *(const float4*)&As[buf][kk][ty * 8 + 4];
            *(float4*)(bb)     = *(const float4*)&Bs[buf][kk][tx * 8];
            *(float4*)(bb + 4) = *(const float4*)&Bs[buf][kk][tx * 8 + 4];
#pragma unroll
            for (int i = 0; i < 8; i++)
#pragma unroll
                for (int j = 0; j < 8; j++) acc[i][j] += a[i] * bb[j];
        }
        if (it < NIT - 1) {
            int nb = buf ^ 1;
            As[nb][a_k + 0][a_r] = nav0.x; As[nb][a_k + 1][a_r] = nav0.y; As[nb][a_k + 2][a_r] = nav0.z; As[nb][a_k + 3][a_r] = nav0.w;
            As[nb][a_k + 4][a_r] = nav1.x; As[nb][a_k + 5][a_r] = nav1.y; As[nb][a_k + 6][a_r] = nav1.z; As[nb][a_k + 7][a_r] = nav1.w;
#pragma unroll
            for (int i = 0; i < 4; i++)
                *(float4*)&Bs[nb][b_row + i * 4][b_col] = nbv[i];
            __syncthreads();
            buf = nb;
        }
    }

#pragma unroll
    for (int i = 0; i < 8; i++) {
        float* crow = Cb + (size_t)(m0 + ty * 8 + i) * HW + n0 + tx * 8;
        *(float4*)(crow)     = make_float4(acc[i][0], acc[i][1], acc[i][2], acc[i][3]);
        *(float4*)(crow + 4) = make_float4(acc[i][4], acc[i][5], acc[i][6], acc[i][7]);
    }
}

// ---------------- kernel 5: depthwise 3x3, pad 1 ----------------
__global__ void dwconv_kernel(const float* __restrict__ wdw) {
    const int bc = blockIdx.z;
    const int c = bc % CCH;
    const int xx = blockIdx.x * 32 + (threadIdx.x & 31);
    const int yy = blockIdx.y * 8 + (threadIdx.x >> 5);
    const float* Yc = g_Y + (size_t)bc * HW;

    float w[9];
#pragma unroll
    for (int i = 0; i < 9; i++) w[i] = wdw[c * 9 + i];

    float acc = 0.f;
#pragma unroll
    for (int ky = 0; ky < 3; ky++) {
        int sy = yy + ky - 1;
        if (sy < 0 || sy >= 128) continue;
#pragma unroll
        for (int kx = 0; kx < 3; kx++) {
            int sx = xx + kx - 1;
            if (sx < 0 || sx >= 128) continue;
            acc += w[ky * 3 + kx] * __ldg(Yc + sy * 128 + sx);
        }
    }
    g_Z[(size_t)bc * HW + yy * 128 + xx] = acc;
}

// ---------------- launch ----------------
extern "C" void kernel_launch(void* const* d_in, const int* in_sizes, int n_in,
                              void* d_out, int out_size) {
    const float* x           = (const float*)d_in[0];
    const float* w_qkv       = (const float*)d_in[1];
    const float* w_dw        = (const float*)d_in[2];
    const float* w_proj      = (const float*)d_in[3];
    const float* temperature = (const float*)d_in[4];
    float* out = (float*)d_out;

    float *pMeff, *pY, *pZ;
    cudaGetSymbolAddress((void**)&pMeff, g_Meff);
    cudaGetSymbolAddress((void**)&pY, g_Y);
    cudaGetSymbolAddress((void**)&pZ, g_Z);

    // 1) S = X X^T (upper-tri split-K partials + deterministic mirror-reduce)
    s_partial_kernel<<<dim3(6, NSPLIT, BATCH), 128>>>(x);
    s_reduce_kernel<<<(BATCH * CCH * CCH + 255) / 256, 256>>>();

    // 2) tiny: G, norms, softmax, Meff
    attn_build_kernel<<<dim3(HEADS, BATCH), 192>>>(w_qkv, temperature);

    // 3) Y = Meff @ X
    gemm192_kernel<<<dim3(HW / 128, 3, BATCH), 128>>>(pMeff, CCH * CCH, x, pY);

    // 4) depthwise 3x3
    dwconv_kernel<<<dim3(4, 16, BATCH * CCH), 256>>>(w_dw);

    // 5) out = Wproj @ Z
    gemm192_kernel<<<dim3(HW / 128, 3, BATCH), 128>>>(w_proj, 0, pZ, out);
}

// round 4
// speedup vs baseline: 1.2465x; 1.0954x over previous
#include <cuda_runtime.h>
#include <math.h>

#define BATCH 8
#define CCH 192
#define HEADS 16
#define HD 12
#define HW 16384
#define NSPLIT 32
#define KCHUNK 512   // HW / NSPLIT

// ---------------- scratch (device globals; no allocation) ----------------
__device__ float g_Spart[BATCH * NSPLIT * CCH * CCH];   // split-K partials (upper tiles only)
__device__ float g_S[BATCH * CCH * CCH];                // X X^T per batch
__device__ float g_Meff[BATCH * CCH * CCH];             // folded attn*Wv per batch
__device__ float g_Y[(size_t)BATCH * CCH * HW];         // attention output (pre-dwconv)
__device__ float g_Z[(size_t)BATCH * CCH * HW];         // dwconv output

// upper-triangular 64x64 tile pairs of the 3x3 tile grid
__constant__ int c_tm[6] = {0, 0, 0, 1, 1, 2};
__constant__ int c_tn[6] = {0, 1, 2, 1, 2, 2};

// ---------------- kernel 1: S partials = X X^T over a K-chunk ----------------
// grid (6, NSPLIT, BATCH), 128 threads. 64x64 tile.
// Warp grid 2x2 (warp tile 32x32), lanes 4(m)x8(n), thread 8m x 4n with split
// m-fragments (+0/+16) -> conflict-free LDS.
__global__ void __launch_bounds__(128, 4) s_partial_kernel(const float* __restrict__ x) {
    const int tm = c_tm[blockIdx.x], tn = c_tn[blockIdx.x];
    const int ks = blockIdx.y, b = blockIdx.z;
    const float* Xb = x + (size_t)b * CCH * HW;
    const int p0 = ks * KCHUNK;

    __shared__ float As[2][16][64];
    __shared__ float Bs[2][16][64];

    const int t  = threadIdx.x;
    const int w  = t >> 5, l = t & 31;
    const int wm = w >> 1, wn = w & 1;
    const int lm = l >> 3, ln = l & 7;
    const int mf = wm * 32 + lm * 4;   // m fragment base (second at +16)
    const int nf = wn * 32 + ln * 4;   // n fragment base (4 wide)

    const int a_r = t & 63, a_k = (t >> 6) * 8;  // loader: 64 rows x 2 k-halves

    const float* Arow = Xb + (size_t)(tm * 64 + a_r) * HW + p0 + a_k;
    const float* Brow = Xb + (size_t)(tn * 64 + a_r) * HW + p0 + a_k;

    float acc[8][4] = {};

    // preload k-block 0
    float4 av0 = *(const float4*)(Arow);
    float4 av1 = *(const float4*)(Arow + 4);
    float4 bv0 = *(const float4*)(Brow);
    float4 bv1 = *(const float4*)(Brow + 4);
    As[0][a_k + 0][a_r] = av0.x; As[0][a_k + 1][a_r] = av0.y; As[0][a_k + 2][a_r] = av0.z; As[0][a_k + 3][a_r] = av0.w;
    As[0][a_k + 4][a_r] = av1.x; As[0][a_k + 5][a_r] = av1.y; As[0][a_k + 6][a_r] = av1.z; As[0][a_k + 7][a_r] = av1.w;
    Bs[0][a_k + 0][a_r] = bv0.x; Bs[0][a_k + 1][a_r] = bv0.y; Bs[0][a_k + 2][a_r] = bv0.z; Bs[0][a_k + 3][a_r] = bv0.w;
    Bs[0][a_k + 4][a_r] = bv1.x; Bs[0][a_k + 5][a_r] = bv1.y; Bs[0][a_k + 6][a_r] = bv1.z; Bs[0][a_k + 7][a_r] = bv1.w;
    __syncthreads();

    int buf = 0;
    const int NIT = KCHUNK / 16;
    for (int it = 0; it < NIT; it++) {
        float4 nav0, nav1, nbv0, nbv1;
        if (it < NIT - 1) {
            const float* Ap = Arow + (it + 1) * 16;
            const float* Bp = Brow + (it + 1) * 16;
            nav0 = *(const float4*)(Ap);     nav1 = *(const float4*)(Ap + 4);
            nbv0 = *(const float4*)(Bp);     nbv1 = *(const float4*)(Bp + 4);
        }
#pragma unroll
        for (int kk = 0; kk < 16; kk++) {
            float a[8], bb[4];
            *(float4*)(a)     = *(const float4*)&As[buf][kk][mf];
            *(float4*)(a + 4) = *(const float4*)&As[buf][kk][mf + 16];
            *(float4*)(bb)    = *(const float4*)&Bs[buf][kk][nf];
#pragma unroll
            for (int i = 0; i < 8; i++)
#pragma unroll
                for (int j = 0; j < 4; j++) acc[i][j] += a[i] * bb[j];
        }
        if (it < NIT - 1) {
            int nb = buf ^ 1;
            As[nb][a_k + 0][a_r] = nav0.x; As[nb][a_k + 1][a_r] = nav0.y; As[nb][a_k + 2][a_r] = nav0.z; As[nb][a_k + 3][a_r] = nav0.w;
            As[nb][a_k + 4][a_r] = nav1.x; As[nb][a_k + 5][a_r] = nav1.y; As[nb][a_k + 6][a_r] = nav1.z; As[nb][a_k + 7][a_r] = nav1.w;
            Bs[nb][a_k + 0][a_r] = nbv0.x; Bs[nb][a_k + 1][a_r] = nbv0.y; Bs[nb][a_k + 2][a_r] = nbv0.z; Bs[nb][a_k + 3][a_r] = nbv0.w;
            Bs[nb][a_k + 4][a_r] = nbv1.x; Bs[nb][a_k + 5][a_r] = nbv1.y; Bs[nb][a_k + 6][a_r] = nbv1.z; Bs[nb][a_k + 7][a_r] = nbv1.w;
            __syncthreads();
            buf = nb;
        }
    }

    float* sp = g_Spart + (size_t)(b * NSPLIT + ks) * CCH * CCH;
#pragma unroll
    for (int i = 0; i < 8; i++) {
        int row = tm * 64 + mf + ((i < 4) ? i : 12 + i);   // +0..3 and +16..19
        *(float4*)(sp + (size_t)row * CCH + tn * 64 + nf) =
            make_float4(acc[i][0], acc[i][1], acc[i][2], acc[i][3]);
    }
}

// ---------------- kernel 2: reduce split-K partials (mirror lower triangle) --
__global__ void s_reduce_kernel() {
    int gid = blockIdx.x * blockDim.x + threadIdx.x;
    if (gid >= BATCH * CCH * CCH) return;
    int b = gid / (CCH * CCH), mn = gid % (CCH * CCH);
    int m = mn / CCH, n = mn % CCH;
    int off = ((m >> 6) <= (n >> 6)) ? (m * CCH + n) : (n * CCH + m);
    const float* base = g_Spart + (size_t)b * NSPLIT * CCH * CCH;
    float s = 0.f;
#pragma unroll 8
    for (int ks = 0; ks < NSPLIT; ks++)
        s += base[(size_t)ks * CCH * CCH + off];
    g_S[gid] = s;
}

// ---------------- kernel 3: per-(b,h) attention -> Meff ----------------
__global__ void attn_build_kernel(const float* __restrict__ w_qkv,
                                  const float* __restrict__ temperature) {
    const int h = blockIdx.x, b = blockIdx.y, t = threadIdx.x;

    __shared__ float sWq[HD][196];
    __shared__ float sWk[HD][196];
    __shared__ float sT[2 * HD][196];   // reused for Wv later
    __shared__ float sG[HD][HD];
    __shared__ float sAttn[HD][HD];
    __shared__ float sQn[HD], sKn[HD];

    for (int i = t; i < HD * CCH; i += 192) {
        int c = i / CCH, j = i % CCH;
        sWq[c][j] = w_qkv[(h * HD + c) * CCH + j];
        sWk[c][j] = w_qkv[(CCH + h * HD + c) * CCH + j];
    }
    __syncthreads();

    // T = [Wq;Wk] * S   (thread t owns column t)
    {
        float tq[HD] = {}, tk[HD] = {};
        const float* Sb = g_S + b * CCH * CCH;
        for (int m = 0; m < CCH; m++) {
            float s = Sb[m * CCH + t];
#pragma unroll
            for (int c = 0; c < HD; c++) { tq[c] += sWq[c][m] * s; tk[c] += sWk[c][m] * s; }
        }
#pragma unroll
        for (int c = 0; c < HD; c++) { sT[c][t] = tq[c]; sT[HD + c][t] = tk[c]; }
    }
    __syncthreads();

    // G and diagonal norms
    if (t < 144) {
        int c = t / HD, d = t % HD;
        float s = 0.f;
        for (int j = 0; j < CCH; j++) s += sT[c][j] * sWk[d][j];
        sG[c][d] = s;
    } else if (t < 156) {
        int c = t - 144; float s = 0.f;
        for (int j = 0; j < CCH; j++) s += sT[c][j] * sWq[c][j];
        sQn[c] = s;
    } else if (t < 168) {
        int c = t - 156; float s = 0.f;
        for (int j = 0; j < CCH; j++) s += sT[HD + c][j] * sWk[c][j];
        sKn[c] = s;
    }
    __syncthreads();

    if (t < HD) {
        float temp = temperature[h];
        float qn = fmaxf(sqrtf(fmaxf(sQn[t], 0.f)), 1e-12f);
        float lg[HD];
        float mx = -1e30f;
#pragma unroll
        for (int d = 0; d < HD; d++) {
            float kn = fmaxf(sqrtf(fmaxf(sKn[d], 0.f)), 1e-12f);
            lg[d] = sG[t][d] * temp / (qn * kn);
            mx = fmaxf(mx, lg[d]);
        }
        float sum = 0.f;
#pragma unroll
        for (int d = 0; d < HD; d++) { lg[d] = expf(lg[d] - mx); sum += lg[d]; }
        float inv = 1.f / sum;
#pragma unroll
        for (int d = 0; d < HD; d++) sAttn[t][d] = lg[d] * inv;
    }
    float (*sWv)[196] = sT;  // reuse
    for (int i = t; i < HD * CCH; i += 192) {
        int c = i / CCH, j = i % CCH;
        sWv[c][j] = w_qkv[(2 * CCH + h * HD + c) * CCH + j];
    }
    __syncthreads();

#pragma unroll
    for (int c = 0; c < HD; c++) {
        float s = 0.f;
#pragma unroll
        for (int d = 0; d < HD; d++) s += sAttn[c][d] * sWv[d][t];
        g_Meff[(size_t)(b * CCH + h * HD + c) * CCH + t] = s;
    }
}

// ---------------- kernel 4: C[b] = A_b[192,192] @ B[b][192,HW] ----------------
// 64x128 tile, 128 threads. Warp grid 2x2 (warp tile 32x64), lanes 4(m)x8(n),
// thread 8x8 with split fragments m:+0/+16, n:+0/+32 -> conflict-free LDS.
// grid (HW/128, 3, BATCH).
__global__ void __launch_bounds__(128, 4) gemm192_kernel(
        const float* __restrict__ A, int aStride,
        const float* __restrict__ B, float* __restrict__ Cout) {
    const float* Ab = A + (size_t)blockIdx.z * aStride;
    const float* Bb = B + (size_t)blockIdx.z * CCH * HW;
    float* Cb = Cout + (size_t)blockIdx.z * CCH * HW;
    const int m0 = blockIdx.y * 64, n0 = blockIdx.x * 128;

    __shared__ float As[2][16][64];
    __shared__ float Bs[2][16][128];

    const int t  = threadIdx.x;
    const int w  = t >> 5, l = t & 31;
    const int wm = w >> 1, wn = w & 1;
    const int lm = l >> 3, ln = l & 7;
    const int mf = wm * 32 + lm * 4;   // m fragment base (second at +16)
    const int nf = wn * 64 + ln * 4;   // n fragment base (second at +32)

    const int a_r = t & 63, a_k = (t >> 6) * 8;      // A load: 64 rows x 2 k-halves
    const int b_row = t >> 5, b_col = (t & 31) * 4;  // B load: 4 rows base, stride 4

    float acc[8][8] = {};

    // preload k-block 0
    const float* Ap0 = Ab + (m0 + a_r) * CCH + a_k;
    float4 av0 = *(const float4*)(Ap0);
    float4 av1 = *(const float4*)(Ap0 + 4);
    float4 bv[4];
#pragma unroll
    for (int i = 0; i < 4; i++)
        bv[i] = *(const float4*)(Bb + (size_t)(b_row + i * 4) * HW + n0 + b_col);

    As[0][a_k + 0][a_r] = av0.x; As[0][a_k + 1][a_r] = av0.y; As[0][a_k + 2][a_r] = av0.z; As[0][a_k + 3][a_r] = av0.w;
    As[0][a_k + 4][a_r] = av1.x; As[0][a_k + 5][a_r] = av1.y; As[0][a_k + 6][a_r] = av1.z; As[0][a_k + 7][a_r] = av1.w;
#pragma unroll
    for (int i = 0; i < 4; i++)
        *(float4*)&Bs[0][b_row + i * 4][b_col] = bv[i];
    __syncthreads();

    int buf = 0;
    const int NIT = CCH / 16;   // 12
    for (int it = 0; it < NIT; it++) {
        float4 nav0, nav1, nbv[4];
        if (it < NIT - 1) {
            int k0 = (it + 1) * 16;
            const float* Ap = Ab + (m0 + a_r) * CCH + k0 + a_k;
            nav0 = *(const float4*)(Ap);
            nav1 = *(const float4*)(Ap + 4);
#pragma unroll
            for (int i = 0; i < 4; i++)
                nbv[i] = *(const float4*)(Bb + (size_t)(k0 + b_row + i * 4) * HW + n0 + b_col);
        }
#pragma unroll
        for (int kk = 0; kk < 16; kk++) {
            float a[8], bb[8];
            *(float4*)(a)      = *(const float4*)&As[buf][kk][mf];
            *(float4*)(a + 4)  = *(const float4*)&As[buf][kk][mf + 16];
            *(float4*)(bb)     = *(const float4*)&Bs[buf][kk][nf];
            *(float4*)(bb + 4) = *(const float4*)&Bs[buf][kk][nf + 32];
#pragma unroll
            for (int i = 0; i < 8; i++)
#pragma unroll
                for (int j = 0; j < 8; j++) acc[i][j] += a[i] * bb[j];
        }
        if (it < NIT - 1) {
            int nb = buf ^ 1;
            As[nb][a_k + 0][a_r] = nav0.x; As[nb][a_k + 1][a_r] = nav0.y; As[nb][a_k + 2][a_r] = nav0.z; As[nb][a_k + 3][a_r] = nav0.w;
            As[nb][a_k + 4][a_r] = nav1.x; As[nb][a_k + 5][a_r] = nav1.y; As[nb][a_k + 6][a_r] = nav1.z; As[nb][a_k + 7][a_r] = nav1.w;
#pragma unroll
            for (int i = 0; i < 4; i++)
                *(float4*)&Bs[nb][b_row + i * 4][b_col] = nbv[i];
            __syncthreads();
            buf = nb;
        }
    }

#pragma unroll
    for (int i = 0; i < 8; i++) {
        int row = m0 + mf + ((i < 4) ? i : 12 + i);   // +0..3 and +16..19
        float* crow = Cb + (size_t)row * HW + n0 + nf;
        *(float4*)(crow)      = make_float4(acc[i][0], acc[i][1], acc[i][2], acc[i][3]);
        *(float4*)(crow + 32) = make_float4(acc[i][4], acc[i][5], acc[i][6], acc[i][7]);
    }
}

// ---------------- kernel 5: depthwise 3x3, pad 1 ----------------
__global__ void dwconv_kernel(const float* __restrict__ wdw) {
    const int bc = blockIdx.z;
    const int c = bc % CCH;
    const int xx = blockIdx.x * 32 + (threadIdx.x & 31);
    const int yy = blockIdx.y * 8 + (threadIdx.x >> 5);
    const float* Yc = g_Y + (size_t)bc * HW;

    float w[9];
#pragma unroll
    for (int i = 0; i < 9; i++) w[i] = wdw[c * 9 + i];

    float acc = 0.f;
#pragma unroll
    for (int ky = 0; ky < 3; ky++) {
        int sy = yy + ky - 1;
        if (sy < 0 || sy >= 128) continue;
#pragma unroll
        for (int kx = 0; kx < 3; kx++) {
            int sx = xx + kx - 1;
            if (sx < 0 || sx >= 128) continue;
            acc += w[ky * 3 + kx] * __ldg(Yc + sy * 128 + sx);
        }
    }
    g_Z[(size_t)bc * HW + yy * 128 + xx] = acc;
}

// ---------------- launch ----------------
extern "C" void kernel_launch(void* const* d_in, const int* in_sizes, int n_in,
                              void* d_out, int out_size) {
    const float* x           = (const float*)d_in[0];
    const float* w_qkv       = (const float*)d_in[1];
    const float* w_dw        = (const float*)d_in[2];
    const float* w_proj      = (const float*)d_in[3];
    const float* temperature = (const float*)d_in[4];
    float* out = (float*)d_out;

    float *pMeff, *pY, *pZ;
    cudaGetSymbolAddress((void**)&pMeff, g_Meff);
    cudaGetSymbolAddress((void**)&pY, g_Y);
    cudaGetSymbolAddress((void**)&pZ, g_Z);

    // 1) S = X X^T (upper-tri split-K partials + deterministic mirror-reduce)
    s_partial_kernel<<<dim3(6, NSPLIT, BATCH), 128>>>(x);
    s_reduce_kernel<<<(BATCH * CCH * CCH + 255) / 256, 256>>>();

    // 2) tiny: G, norms, softmax, Meff
    attn_build_kernel<<<dim3(HEADS, BATCH), 192>>>(w_qkv, temperature);

    // 3) Y = Meff @ X
    gemm192_kernel<<<dim3(HW / 128, 3, BATCH), 128>>>(pMeff, CCH * CCH, x, pY);

    // 4) depthwise 3x3
    dwconv_kernel<<<dim3(4, 16, BATCH * CCH), 256>>>(w_dw);

    // 5) out = Wproj @ Z
    gemm192_kernel<<<dim3(HW / 128, 3, BATCH), 128>>>(w_proj, 0, pZ, out);
}

// round 6
// speedup vs baseline: 1.5836x; 1.2704x over previous
#include <cuda_runtime.h>
#include <cuda_bf16.h>
#include <math.h>
#include <stdint.h>

#define BATCH 8
#define CCH 192
#define HEADS 16
#define HD 12
#define HW 16384
#define NSPLIT 32
#define KCHUNK 512   // HW / NSPLIT

// ---------------- scratch (device globals; no allocation) ----------------
__device__ float g_Spart[BATCH * NSPLIT * CCH * CCH];
__device__ float g_S[BATCH * CCH * CCH];
__device__ float g_Y[(size_t)BATCH * CCH * HW];                 // attention output fp32
__device__ unsigned short g_MHi[BATCH * CCH * CCH];             // Meff bf16 hi
__device__ unsigned short g_MLo[BATCH * CCH * CCH];             // Meff bf16 lo
__device__ unsigned short g_WHi[CCH * CCH];                     // Wproj bf16 hi
__device__ unsigned short g_WLo[CCH * CCH];
__device__ unsigned short g_XThi[(size_t)BATCH * HW * CCH];     // X^T bf16 hi  [b][p][k]
__device__ unsigned short g_XTlo[(size_t)BATCH * HW * CCH];
__device__ unsigned short g_ZThi[(size_t)BATCH * HW * CCH];     // dw(Y)^T bf16 hi [b][p][c]
__device__ unsigned short g_ZTlo[(size_t)BATCH * HW * CCH];

__constant__ int c_tm[6] = {0, 0, 0, 1, 1, 2};
__constant__ int c_tn[6] = {0, 1, 2, 1, 2, 2};

__device__ __forceinline__ void split_bf16(float v, unsigned short& h, unsigned short& l) {
    __nv_bfloat16 bh = __float2bfloat16(v);
    float hf = __bfloat162float(bh);
    __nv_bfloat16 bl = __float2bfloat16(v - hf);
    h = __bfloat16_as_ushort(bh);
    l = __bfloat16_as_ushort(bl);
}

__device__ __forceinline__ uint32_t smem_to_u32(const void* smem_ptr) {
    uint32_t addr;
    asm("{ .reg .u64 tmp; cvta.to.shared.u64 tmp, %1; cvt.u32.u64 %0, tmp; }"
        : "=r"(addr) : "l"(smem_ptr));
    return addr;
}
__device__ __forceinline__ void cp_async16(uint32_t dst, const void* src) {
    asm volatile("cp.async.cg.shared.global [%0], [%1], 16;" :: "r"(dst), "l"(src) : "memory");
}
#define CP_COMMIT() asm volatile("cp.async.commit_group;" ::: "memory")
#define CP_WAIT(n)  asm volatile("cp.async.wait_group %0;" :: "n"(n) : "memory")

__device__ __forceinline__ void mma_bf16(float* c, const uint32_t* a, const uint32_t* b) {
    asm volatile(
        "mma.sync.aligned.m16n8k16.row.col.f32.bf16.bf16.f32 "
        "{%0,%1,%2,%3}, {%4,%5,%6,%7}, {%8,%9}, {%0,%1,%2,%3};"
        : "+f"(c[0]), "+f"(c[1]), "+f"(c[2]), "+f"(c[3])
        : "r"(a[0]), "r"(a[1]), "r"(a[2]), "r"(a[3]), "r"(b[0]), "r"(b[1]));
}

// ---------------- kernel 1: S partials = X X^T over a K-chunk (scalar) -------
__global__ void __launch_bounds__(128, 4) s_partial_kernel(const float* __restrict__ x) {
    const int tm = c_tm[blockIdx.x], tn = c_tn[blockIdx.x];
    const int ks = blockIdx.y, b = blockIdx.z;
    const float* Xb = x + (size_t)b * CCH * HW;
    const int p0 = ks * KCHUNK;

    __shared__ float As[2][16][64];
    __shared__ float Bs[2][16][64];

    const int t  = threadIdx.x;
    const int w  = t >> 5, l = t & 31;
    const int wm = w >> 1, wn = w & 1;
    const int lm = l >> 3, ln = l & 7;
    const int mf = wm * 32 + lm * 4;
    const int nf = wn * 32 + ln * 4;
    const int a_r = t & 63, a_k = (t >> 6) * 8;

    const float* Arow = Xb + (size_t)(tm * 64 + a_r) * HW + p0 + a_k;
    const float* Brow = Xb + (size_t)(tn * 64 + a_r) * HW + p0 + a_k;

    float acc[8][4] = {};

    float4 av0 = *(const float4*)(Arow);
    float4 av1 = *(const float4*)(Arow + 4);
    float4 bv0 = *(const float4*)(Brow);
    float4 bv1 = *(const float4*)(Brow + 4);
    As[0][a_k + 0][a_r] = av0.x; As[0][a_k + 1][a_r] = av0.y; As[0][a_k + 2][a_r] = av0.z; As[0][a_k + 3][a_r] = av0.w;
    As[0][a_k + 4][a_r] = av1.x; As[0][a_k + 5][a_r] = av1.y; As[0][a_k + 6][a_r] = av1.z; As[0][a_k + 7][a_r] = av1.w;
    Bs[0][a_k + 0][a_r] = bv0.x; Bs[0][a_k + 1][a_r] = bv0.y; Bs[0][a_k + 2][a_r] = bv0.z; Bs[0][a_k + 3][a_r] = bv0.w;
    Bs[0][a_k + 4][a_r] = bv1.x; Bs[0][a_k + 5][a_r] = bv1.y; Bs[0][a_k + 6][a_r] = bv1.z; Bs[0][a_k + 7][a_r] = bv1.w;
    __syncthreads();

    int buf = 0;
    const int NIT = KCHUNK / 16;
    for (int it = 0; it < NIT; it++) {
        float4 nav0, nav1, nbv0, nbv1;
        if (it < NIT - 1) {
            const float* Ap = Arow + (it + 1) * 16;
            const float* Bp = Brow + (it + 1) * 16;
            nav0 = *(const float4*)(Ap);     nav1 = *(const float4*)(Ap + 4);
            nbv0 = *(const float4*)(Bp);     nbv1 = *(const float4*)(Bp + 4);
        }
#pragma unroll
        for (int kk = 0; kk < 16; kk++) {
            float a[8], bb[4];
            *(float4*)(a)     = *(const float4*)&As[buf][kk][mf];
            *(float4*)(a + 4) = *(const float4*)&As[buf][kk][mf + 16];
            *(float4*)(bb)    = *(const float4*)&Bs[buf][kk][nf];
#pragma unroll
            for (int i = 0; i < 8; i++)
#pragma unroll
                for (int j = 0; j < 4; j++) acc[i][j] += a[i] * bb[j];
        }
        if (it < NIT - 1) {
            int nb = buf ^ 1;
            As[nb][a_k + 0][a_r] = nav0.x; As[nb][a_k + 1][a_r] = nav0.y; As[nb][a_k + 2][a_r] = nav0.z; As[nb][a_k + 3][a_r] = nav0.w;
            As[nb][a_k + 4][a_r] = nav1.x; As[nb][a_k + 5][a_r] = nav1.y; As[nb][a_k + 6][a_r] = nav1.z; As[nb][a_k + 7][a_r] = nav1.w;
            Bs[nb][a_k + 0][a_r] = nbv0.x; Bs[nb][a_k + 1][a_r] = nbv0.y; Bs[nb][a_k + 2][a_r] = nbv0.z; Bs[nb][a_k + 3][a_r] = nbv0.w;
            Bs[nb][a_k + 4][a_r] = nbv1.x; Bs[nb][a_k + 5][a_r] = nbv1.y; Bs[nb][a_k + 6][a_r] = nbv1.z; Bs[nb][a_k + 7][a_r] = nbv1.w;
            __syncthreads();
            buf = nb;
        }
    }

    float* sp = g_Spart + (size_t)(b * NSPLIT + ks) * CCH * CCH;
#pragma unroll
    for (int i = 0; i < 8; i++) {
        int row = tm * 64 + mf + ((i < 4) ? i : 12 + i);
        *(float4*)(sp + (size_t)row * CCH + tn * 64 + nf) =
            make_float4(acc[i][0], acc[i][1], acc[i][2], acc[i][3]);
    }
}

// ---------------- kernel 2: reduce split-K partials (mirror lower) ----------
__global__ void s_reduce_kernel() {
    int gid = blockIdx.x * blockDim.x + threadIdx.x;
    if (gid >= BATCH * CCH * CCH) return;
    int b = gid / (CCH * CCH), mn = gid % (CCH * CCH);
    int m = mn / CCH, n = mn % CCH;
    int off = ((m >> 6) <= (n >> 6)) ? (m * CCH + n) : (n * CCH + m);
    const float* base = g_Spart + (size_t)b * NSPLIT * CCH * CCH;
    float s = 0.f;
#pragma unroll 8
    for (int ks = 0; ks < NSPLIT; ks++)
        s += base[(size_t)ks * CCH * CCH + off];
    g_S[gid] = s;
}

// ---------------- kernel 3: per-(b,h) attention -> Meff (bf16 hi/lo) --------
__global__ void attn_build_kernel(const float* __restrict__ w_qkv,
                                  const float* __restrict__ temperature) {
    const int h = blockIdx.x, b = blockIdx.y, t = threadIdx.x;

    __shared__ float sWq[HD][196];
    __shared__ float sWk[HD][196];
    __shared__ float sT[2 * HD][196];
    __shared__ float sG[HD][HD];
    __shared__ float sAttn[HD][HD];
    __shared__ float sQn[HD], sKn[HD];

    for (int i = t; i < HD * CCH; i += 192) {
        int c = i / CCH, j = i % CCH;
        sWq[c][j] = w_qkv[(h * HD + c) * CCH + j];
        sWk[c][j] = w_qkv[(CCH + h * HD + c) * CCH + j];
    }
    __syncthreads();

    {
        float tq[HD] = {}, tk[HD] = {};
        const float* Sb = g_S + b * CCH * CCH;
        for (int m = 0; m < CCH; m++) {
            float s = Sb[m * CCH + t];
#pragma unroll
            for (int c = 0; c < HD; c++) { tq[c] += sWq[c][m] * s; tk[c] += sWk[c][m] * s; }
        }
#pragma unroll
        for (int c = 0; c < HD; c++) { sT[c][t] = tq[c]; sT[HD + c][t] = tk[c]; }
    }
    __syncthreads();

    if (t < 144) {
        int c = t / HD, d = t % HD;
        float s = 0.f;
        for (int j = 0; j < CCH; j++) s += sT[c][j] * sWk[d][j];
        sG[c][d] = s;
    } else if (t < 156) {
        int c = t - 144; float s = 0.f;
        for (int j = 0; j < CCH; j++) s += sT[c][j] * sWq[c][j];
        sQn[c] = s;
    } else if (t < 168) {
        int c = t - 156; float s = 0.f;
        for (int j = 0; j < CCH; j++) s += sT[HD + c][j] * sWk[c][j];
        sKn[c] = s;
    }
    __syncthreads();

    if (t < HD) {
        float temp = temperature[h];
        float qn = fmaxf(sqrtf(fmaxf(sQn[t], 0.f)), 1e-12f);
        float lg[HD];
        float mx = -1e30f;
#pragma unroll
        for (int d = 0; d < HD; d++) {
            float kn = fmaxf(sqrtf(fmaxf(sKn[d], 0.f)), 1e-12f);
            lg[d] = sG[t][d] * temp / (qn * kn);
            mx = fmaxf(mx, lg[d]);
        }
        float sum = 0.f;
#pragma unroll
        for (int d = 0; d < HD; d++) { lg[d] = expf(lg[d] - mx); sum += lg[d]; }
        float inv = 1.f / sum;
#pragma unroll
        for (int d = 0; d < HD; d++) sAttn[t][d] = lg[d] * inv;
    }
    float (*sWv)[196] = sT;
    for (int i = t; i < HD * CCH; i += 192) {
        int c = i / CCH, j = i % CCH;
        sWv[c][j] = w_qkv[(2 * CCH + h * HD + c) * CCH + j];
    }
    __syncthreads();

#pragma unroll
    for (int c = 0; c < HD; c++) {
        float s = 0.f;
#pragma unroll
        for (int d = 0; d < HD; d++) s += sAttn[c][d] * sWv[d][t];
        size_t idx = (size_t)(b * CCH + h * HD + c) * CCH + t;
        unsigned short hh, ll;
        split_bf16(s, hh, ll);
        g_MHi[idx] = hh; g_MLo[idx] = ll;
    }
}

// ---------------- kernel 3b: Wproj -> bf16 hi/lo ----------------------------
__global__ void wconv_kernel(const float* __restrict__ w_proj) {
    int gid = blockIdx.x * blockDim.x + threadIdx.x;
    if (gid >= CCH * CCH) return;
    unsigned short hh, ll;
    split_bf16(w_proj[gid], hh, ll);
    g_WHi[gid] = hh; g_WLo[gid] = ll;
}

// ---------------- kernel 3c: X -> X^T bf16 hi/lo [b][p][k] -------------------
__global__ void xt_kernel(const float* __restrict__ x) {
    const int b = blockIdx.z;
    const int k0 = blockIdx.y * 32, p0 = blockIdx.x * 32;
    __shared__ float sm[32][33];
    const int tx = threadIdx.x & 31, ty = threadIdx.x >> 5;

#pragma unroll
    for (int i = 0; i < 4; i++) {
        int k = k0 + ty + i * 8;
        sm[ty + i * 8][tx] = x[((size_t)b * CCH + k) * HW + p0 + tx];
    }
    __syncthreads();
#pragma unroll
    for (int i = 0; i < 4; i++) {
        int p = p0 + ty + i * 8;
        int k = k0 + tx;
        float v = sm[tx][ty + i * 8];
        unsigned short hh, ll;
        split_bf16(v, hh, ll);
        size_t o = ((size_t)b * HW + p) * CCH + k;
        g_XThi[o] = hh;
        g_XTlo[o] = ll;
    }
}

// ---------------- kernel 4: mma.sync GEMM  C[b] = A[b] @ B[b]^T ---------------
// A:  bf16 hi/lo [192,192] row-major (aStride elems per batch; 0 = shared)
// BT: bf16 hi/lo [b][p][192]  (K contiguous)
// C:  fp32 [b][192][HW]
// Block: M=192 x N=128, 256 threads (warp grid 4m x 2n, warp tile 48x64).
// K chunks of 32, cp.async double-buffered. 3-pass split bf16.
#define SA32 20                 // smem row stride in u32 (40 bf16)
#define BUF_U32 12800           // per-buffer u32 size
#define OFF_ALO 3840
#define OFF_BHI 7680
#define OFF_BLO 10240
#define GEMM_SMEM (2 * BUF_U32 * 4)   // 102400 bytes

__global__ void __launch_bounds__(256, 1)
gemm_mma_kernel(const unsigned short* __restrict__ Ahi,
                const unsigned short* __restrict__ Alo,
                size_t aStride,
                const unsigned short* __restrict__ BThi,
                const unsigned short* __restrict__ BTlo,
                float* __restrict__ C) {
    extern __shared__ uint32_t sm32[];
    const int t = threadIdx.x;
    const int b = blockIdx.z;
    const int n0 = blockIdx.x * 128;
    const int warp = t >> 5, lane = t & 31;
    const int wm = warp & 3, wn = warp >> 2;
    const int warpM = wm * 48, warpN = wn * 64;
    const int gr = lane >> 2, qp = lane & 3;

    const unsigned short* Ah = Ahi + (size_t)b * aStride;
    const unsigned short* Al = Alo + (size_t)b * aStride;
    const unsigned short* Bh = BThi + ((size_t)b * HW + n0) * CCH;
    const unsigned short* Bl = BTlo + ((size_t)b * HW + n0) * CCH;

    const uint32_t smbase = smem_to_u32(sm32);

    float acc[3][8][4] = {};

    // ---- cp.async chunk loader ----
    auto issue_chunk = [&](int buf, int kc) {
        const uint32_t sb = smbase + buf * (BUF_U32 * 4);
        const int kb = kc * 32;
        // A: 192 rows x 4 quads (16B) per stream; 768 items, 3 per thread
#pragma unroll
        for (int i = t; i < 768; i += 256) {
            int row = i >> 2, q = i & 3;
            uint32_t dst = sb + (row * SA32 + q * 4) * 4;
            cp_async16(dst,                Ah + (size_t)row * CCH + kb + q * 8);
            cp_async16(dst + OFF_ALO * 4,  Al + (size_t)row * CCH + kb + q * 8);
        }
        // B: 128 rows x 4 quads per stream; 512 items, 2 per thread
#pragma unroll
        for (int i = t; i < 512; i += 256) {
            int row = i >> 2, q = i & 3;
            uint32_t dst = sb + (OFF_BHI + row * SA32 + q * 4) * 4;
            cp_async16(dst,                       Bh + (size_t)row * CCH + kb + q * 8);
            cp_async16(dst + (OFF_BLO - OFF_BHI) * 4, Bl + (size_t)row * CCH + kb + q * 8);
        }
        CP_COMMIT();
    };

    issue_chunk(0, 0);

    int buf = 0;
    for (int kc = 0; kc < 6; kc++) {
        if (kc < 5) {
            issue_chunk(buf ^ 1, kc + 1);
            CP_WAIT(1);
        } else {
            CP_WAIT(0);
        }
        __syncthreads();

        const uint32_t* S = sm32 + buf * BUF_U32;
#pragma unroll
        for (int ks = 0; ks < 2; ks++) {
            const int k8 = ks * 8;
            uint32_t ah[3][4], al[3][4], bh[8][2], bl[8][2];
#pragma unroll
            for (int mt = 0; mt < 3; mt++) {
                int base = (warpM + mt * 16 + gr) * SA32 + k8 + qp;
                ah[mt][0] = S[base];           ah[mt][1] = S[base + 8 * SA32];
                ah[mt][2] = S[base + 4];       ah[mt][3] = S[base + 8 * SA32 + 4];
                al[mt][0] = S[OFF_ALO + base];           al[mt][1] = S[OFF_ALO + base + 8 * SA32];
                al[mt][2] = S[OFF_ALO + base + 4];       al[mt][3] = S[OFF_ALO + base + 8 * SA32 + 4];
            }
#pragma unroll
            for (int nt = 0; nt < 8; nt++) {
                int base = (warpN + nt * 8 + gr) * SA32 + k8 + qp;
                bh[nt][0] = S[OFF_BHI + base]; bh[nt][1] = S[OFF_BHI + base + 4];
                bl[nt][0] = S[OFF_BLO + base]; bl[nt][1] = S[OFF_BLO + base + 4];
            }
#pragma unroll
            for (int mt = 0; mt < 3; mt++)
#pragma unroll
                for (int nt = 0; nt < 8; nt++) {
                    mma_bf16(acc[mt][nt], ah[mt], bh[nt]);
                    mma_bf16(acc[mt][nt], ah[mt], bl[nt]);
                    mma_bf16(acc[mt][nt], al[mt], bh[nt]);
                }
        }
        __syncthreads();
        buf ^= 1;
    }

    // ---- epilogue ----
#pragma unroll
    for (int mt = 0; mt < 3; mt++) {
        int m = warpM + mt * 16 + gr;
        float* c0 = C + ((size_t)b * CCH + m) * HW + n0 + warpN + qp * 2;
        float* c1 = C + ((size_t)b * CCH + m + 8) * HW + n0 + warpN + qp * 2;
#pragma unroll
        for (int nt = 0; nt < 8; nt++) {
            *(float2*)(c0 + nt * 8) = make_float2(acc[mt][nt][0], acc[mt][nt][1]);
            *(float2*)(c1 + nt * 8) = make_float2(acc[mt][nt][2], acc[mt][nt][3]);
        }
    }
}

// ---------------- kernel 6: depthwise 3x3 -> Z^T bf16 hi/lo [b][p][c] --------
__global__ void dwconv_t_kernel(const float* __restrict__ wdw) {
    const int b = blockIdx.z;
    const int c0 = blockIdx.y * 32;
    const int p0 = blockIdx.x * 32;
    const int y  = p0 >> 7;
    const int x0 = p0 & 127;

    __shared__ float sw[32][9];
    __shared__ float st[32][33];   // [px][chLocal]

    const int t = threadIdx.x;
    for (int idx = t; idx < 288; idx += 256)
        sw[idx / 9][idx % 9] = wdw[(c0 + idx / 9) * 9 + idx % 9];
    __syncthreads();

    const int tx = t & 31;      // px
    const int tg = t >> 5;      // 0..7
    const int xx = x0 + tx;

#pragma unroll
    for (int i = 0; i < 4; i++) {
        int chL = tg + i * 8;
        const float* Yc = g_Y + ((size_t)b * CCH + c0 + chL) * HW;
        float acc = 0.f;
#pragma unroll
        for (int ky = 0; ky < 3; ky++) {
            int sy = y + ky - 1;
            if (sy < 0 || sy >= 128) continue;
#pragma unroll
            for (int kx = 0; kx < 3; kx++) {
                int sx = xx + kx - 1;
                if (sx < 0 || sx >= 128) continue;
                acc += sw[chL][ky * 3 + kx] * __ldg(Yc + sy * 128 + sx);
            }
        }
        st[tx][chL] = acc;
    }
    __syncthreads();

    const int row = t >> 3;
    const int ch4 = (t & 7) * 4;
    float v0 = st[row][ch4 + 0], v1 = st[row][ch4 + 1];
    float v2 = st[row][ch4 + 2], v3 = st[row][ch4 + 3];
    unsigned short h0, l0, h1, l1, h2, l2, h3, l3;
    split_bf16(v0, h0, l0); split_bf16(v1, h1, l1);
    split_bf16(v2, h2, l2); split_bf16(v3, h3, l3);
    size_t o = ((size_t)b * HW + p0 + row) * CCH + c0 + ch4;
    *(uint32_t*)(g_ZThi + o)     = (uint32_t)h0 | ((uint32_t)h1 << 16);
    *(uint32_t*)(g_ZThi + o + 2) = (uint32_t)h2 | ((uint32_t)h3 << 16);
    *(uint32_t*)(g_ZTlo + o)     = (uint32_t)l0 | ((uint32_t)l1 << 16);
    *(uint32_t*)(g_ZTlo + o + 2) = (uint32_t)l2 | ((uint32_t)l3 << 16);
}

// ---------------- launch ----------------
extern "C" void kernel_launch(void* const* d_in, const int* in_sizes, int n_in,
                              void* d_out, int out_size) {
    const float* x           = (const float*)d_in[0];
    const float* w_qkv       = (const float*)d_in[1];
    const float* w_dw        = (const float*)d_in[2];
    const float* w_proj      = (const float*)d_in[3];
    const float* temperature = (const float*)d_in[4];
    float* out = (float*)d_out;

    cudaFuncSetAttribute(gemm_mma_kernel,
                         cudaFuncAttributeMaxDynamicSharedMemorySize, GEMM_SMEM);

    float* pY;
    unsigned short *pMHi, *pMLo, *pWHi, *pWLo, *pXThi, *pXTlo, *pZThi, *pZTlo;
    cudaGetSymbolAddress((void**)&pY, g_Y);
    cudaGetSymbolAddress((void**)&pMHi, g_MHi);
    cudaGetSymbolAddress((void**)&pMLo, g_MLo);
    cudaGetSymbolAddress((void**)&pWHi, g_WHi);
    cudaGetSymbolAddress((void**)&pWLo, g_WLo);
    cudaGetSymbolAddress((void**)&pXThi, g_XThi);
    cudaGetSymbolAddress((void**)&pXTlo, g_XTlo);
    cudaGetSymbolAddress((void**)&pZThi, g_ZThi);
    cudaGetSymbolAddress((void**)&pZTlo, g_ZTlo);

    // 1) S = X X^T
    s_partial_kernel<<<dim3(6, NSPLIT, BATCH), 128>>>(x);
    s_reduce_kernel<<<(BATCH * CCH * CCH + 255) / 256, 256>>>();

    // 2) attention -> Meff (bf16 hi/lo), Wproj convert, X transpose+convert
    attn_build_kernel<<<dim3(HEADS, BATCH), 192>>>(w_qkv, temperature);
    wconv_kernel<<<(CCH * CCH + 255) / 256, 256>>>(w_proj);
    xt_kernel<<<dim3(HW / 32, CCH / 32, BATCH), 256>>>(x);

    // 3) Y = Meff @ X   (mma.sync split-bf16)
    gemm_mma_kernel<<<dim3(HW / 128, 1, BATCH), 256, GEMM_SMEM>>>(
        pMHi, pMLo, (size_t)CCH * CCH, pXThi, pXTlo, pY);

    // 4) depthwise 3x3 -> Z^T bf16 hi/lo
    dwconv_t_kernel<<<dim3(HW / 32, CCH / 32, BATCH), 256>>>(w_dw);

    // 5) out = Wproj @ Z   (mma.sync split-bf16)
    gemm_mma_kernel<<<dim3(HW / 128, 1, BATCH), 256, GEMM_SMEM>>>(
        pWHi, pWLo, (size_t)0, pZThi, pZTlo, out);
}

// round 7
// speedup vs baseline: 1.5856x; 1.0012x over previous
#include <cuda_runtime.h>
#include <cuda_bf16.h>
#include <math.h>
#include <stdint.h>

#define BATCH 8
#define CCH 192
#define HEADS 16
#define HD 12
#define HW 16384
#define NSPLIT 32
#define KCHUNK 512   // HW / NSPLIT

// ---------------- scratch (device globals; no allocation) ----------------
__device__ float g_Spart[BATCH * NSPLIT * CCH * CCH];
__device__ float g_S[BATCH * CCH * CCH];
__device__ float g_Y[(size_t)BATCH * CCH * HW];                 // attention output fp32
__device__ unsigned short g_MHi[BATCH * CCH * CCH];             // Meff bf16 hi
__device__ unsigned short g_MLo[BATCH * CCH * CCH];             // Meff bf16 lo
__device__ unsigned short g_WHi[CCH * CCH];                     // Wproj bf16 hi
__device__ unsigned short g_WLo[CCH * CCH];
__device__ unsigned short g_XThi[(size_t)BATCH * HW * CCH];     // X^T bf16 hi  [b][p][k]
__device__ unsigned short g_XTlo[(size_t)BATCH * HW * CCH];
__device__ unsigned short g_ZThi[(size_t)BATCH * HW * CCH];     // dw(Y)^T bf16 hi [b][p][c]
__device__ unsigned short g_ZTlo[(size_t)BATCH * HW * CCH];

__constant__ int c_tm[6] = {0, 0, 0, 1, 1, 2};
__constant__ int c_tn[6] = {0, 1, 2, 1, 2, 2};

__device__ __forceinline__ void split_bf16(float v, unsigned short& h, unsigned short& l) {
    __nv_bfloat16 bh = __float2bfloat16(v);
    float hf = __bfloat162float(bh);
    __nv_bfloat16 bl = __float2bfloat16(v - hf);
    h = __bfloat16_as_ushort(bh);
    l = __bfloat16_as_ushort(bl);
}

__device__ __forceinline__ uint32_t smem_to_u32(const void* smem_ptr) {
    uint32_t addr;
    asm("{ .reg .u64 tmp; cvta.to.shared.u64 tmp, %1; cvt.u32.u64 %0, tmp; }"
        : "=r"(addr) : "l"(smem_ptr));
    return addr;
}
__device__ __forceinline__ void cp_async16(uint32_t dst, const void* src) {
    asm volatile("cp.async.cg.shared.global [%0], [%1], 16;" :: "r"(dst), "l"(src) : "memory");
}
#define CP_COMMIT() asm volatile("cp.async.commit_group;" ::: "memory")
#define CP_WAIT(n)  asm volatile("cp.async.wait_group %0;" :: "n"(n) : "memory")

__device__ __forceinline__ void mma_bf16(float* c, const uint32_t* a, const uint32_t* b) {
    asm volatile(
        "mma.sync.aligned.m16n8k16.row.col.f32.bf16.bf16.f32 "
        "{%0,%1,%2,%3}, {%4,%5,%6,%7}, {%8,%9}, {%0,%1,%2,%3};"
        : "+f"(c[0]), "+f"(c[1]), "+f"(c[2]), "+f"(c[3])
        : "r"(a[0]), "r"(a[1]), "r"(a[2]), "r"(a[3]), "r"(b[0]), "r"(b[1]));
}

// ---------------- kernel 1: S partials = X X^T over a K-chunk (scalar) -------
__global__ void __launch_bounds__(128, 4) s_partial_kernel(const float* __restrict__ x) {
    const int tm = c_tm[blockIdx.x], tn = c_tn[blockIdx.x];
    const int ks = blockIdx.y, b = blockIdx.z;
    const float* Xb = x + (size_t)b * CCH * HW;
    const int p0 = ks * KCHUNK;

    __shared__ float As[2][16][64];
    __shared__ float Bs[2][16][64];

    const int t  = threadIdx.x;
    const int w  = t >> 5, l = t & 31;
    const int wm = w >> 1, wn = w & 1;
    const int lm = l >> 3, ln = l & 7;
    const int mf = wm * 32 + lm * 4;
    const int nf = wn * 32 + ln * 4;
    const int a_r = t & 63, a_k = (t >> 6) * 8;

    const float* Arow = Xb + (size_t)(tm * 64 + a_r) * HW + p0 + a_k;
    const float* Brow = Xb + (size_t)(tn * 64 + a_r) * HW + p0 + a_k;

    float acc[8][4] = {};

    float4 av0 = *(const float4*)(Arow);
    float4 av1 = *(const float4*)(Arow + 4);
    float4 bv0 = *(const float4*)(Brow);
    float4 bv1 = *(const float4*)(Brow + 4);
    As[0][a_k + 0][a_r] = av0.x; As[0][a_k + 1][a_r] = av0.y; As[0][a_k + 2][a_r] = av0.z; As[0][a_k + 3][a_r] = av0.w;
    As[0][a_k + 4][a_r] = av1.x; As[0][a_k + 5][a_r] = av1.y; As[0][a_k + 6][a_r] = av1.z; As[0][a_k + 7][a_r] = av1.w;
    Bs[0][a_k + 0][a_r] = bv0.x; Bs[0][a_k + 1][a_r] = bv0.y; Bs[0][a_k + 2][a_r] = bv0.z; Bs[0][a_k + 3][a_r] = bv0.w;
    Bs[0][a_k + 4][a_r] = bv1.x; Bs[0][a_k + 5][a_r] = bv1.y; Bs[0][a_k + 6][a_r] = bv1.z; Bs[0][a_k + 7][a_r] = bv1.w;
    __syncthreads();

    int buf = 0;
    const int NIT = KCHUNK / 16;
    for (int it = 0; it < NIT; it++) {
        float4 nav0, nav1, nbv0, nbv1;
        if (it < NIT - 1) {
            const float* Ap = Arow + (it + 1) * 16;
            const float* Bp = Brow + (it + 1) * 16;
            nav0 = *(const float4*)(Ap);     nav1 = *(const float4*)(Ap + 4);
            nbv0 = *(const float4*)(Bp);     nbv1 = *(const float4*)(Bp + 4);
        }
#pragma unroll
        for (int kk = 0; kk < 16; kk++) {
            float a[8], bb[4];
            *(float4*)(a)     = *(const float4*)&As[buf][kk][mf];
            *(float4*)(a + 4) = *(const float4*)&As[buf][kk][mf + 16];
            *(float4*)(bb)    = *(const float4*)&Bs[buf][kk][nf];
#pragma unroll
            for (int i = 0; i < 8; i++)
#pragma unroll
                for (int j = 0; j < 4; j++) acc[i][j] += a[i] * bb[j];
        }
        if (it < NIT - 1) {
            int nb = buf ^ 1;
            As[nb][a_k + 0][a_r] = nav0.x; As[nb][a_k + 1][a_r] = nav0.y; As[nb][a_k + 2][a_r] = nav0.z; As[nb][a_k + 3][a_r] = nav0.w;
            As[nb][a_k + 4][a_r] = nav1.x; As[nb][a_k + 5][a_r] = nav1.y; As[nb][a_k + 6][a_r] = nav1.z; As[nb][a_k + 7][a_r] = nav1.w;
            Bs[nb][a_k + 0][a_r] = nbv0.x; Bs[nb][a_k + 1][a_r] = nbv0.y; Bs[nb][a_k + 2][a_r] = nbv0.z; Bs[nb][a_k + 3][a_r] = nbv0.w;
            Bs[nb][a_k + 4][a_r] = nbv1.x; Bs[nb][a_k + 5][a_r] = nbv1.y; Bs[nb][a_k + 6][a_r] = nbv1.z; Bs[nb][a_k + 7][a_r] = nbv1.w;
            __syncthreads();
            buf = nb;
        }
    }

    float* sp = g_Spart + (size_t)(b * NSPLIT + ks) * CCH * CCH;
#pragma unroll
    for (int i = 0; i < 8; i++) {
        int row = tm * 64 + mf + ((i < 4) ? i : 12 + i);
        *(float4*)(sp + (size_t)row * CCH + tn * 64 + nf) =
            make_float4(acc[i][0], acc[i][1], acc[i][2], acc[i][3]);
    }
}

// ---------------- kernel 2: reduce split-K partials (mirror lower) ----------
__global__ void s_reduce_kernel() {
    int gid = blockIdx.x * blockDim.x + threadIdx.x;
    if (gid >= BATCH * CCH * CCH) return;
    int b = gid / (CCH * CCH), mn = gid % (CCH * CCH);
    int m = mn / CCH, n = mn % CCH;
    int off = ((m >> 6) <= (n >> 6)) ? (m * CCH + n) : (n * CCH + m);
    const float* base = g_Spart + (size_t)b * NSPLIT * CCH * CCH;
    float s = 0.f;
#pragma unroll 8
    for (int ks = 0; ks < NSPLIT; ks++)
        s += base[(size_t)ks * CCH * CCH + off];
    g_S[gid] = s;
}

// ---------------- kernel 3: per-(b,h) attention -> Meff (bf16 hi/lo) --------
__global__ void attn_build_kernel(const float* __restrict__ w_qkv,
                                  const float* __restrict__ temperature) {
    const int h = blockIdx.x, b = blockIdx.y, t = threadIdx.x;

    __shared__ float sWq[HD][196];
    __shared__ float sWk[HD][196];
    __shared__ float sT[2 * HD][196];
    __shared__ float sG[HD][HD];
    __shared__ float sAttn[HD][HD];
    __shared__ float sQn[HD], sKn[HD];

    for (int i = t; i < HD * CCH; i += 192) {
        int c = i / CCH, j = i % CCH;
        sWq[c][j] = w_qkv[(h * HD + c) * CCH + j];
        sWk[c][j] = w_qkv[(CCH + h * HD + c) * CCH + j];
    }
    __syncthreads();

    {
        float tq[HD] = {}, tk[HD] = {};
        const float* Sb = g_S + b * CCH * CCH;
        for (int m = 0; m < CCH; m++) {
            float s = Sb[m * CCH + t];
#pragma unroll
            for (int c = 0; c < HD; c++) { tq[c] += sWq[c][m] * s; tk[c] += sWk[c][m] * s; }
        }
#pragma unroll
        for (int c = 0; c < HD; c++) { sT[c][t] = tq[c]; sT[HD + c][t] = tk[c]; }
    }
    __syncthreads();

    if (t < 144) {
        int c = t / HD, d = t % HD;
        float s = 0.f;
        for (int j = 0; j < CCH; j++) s += sT[c][j] * sWk[d][j];
        sG[c][d] = s;
    } else if (t < 156) {
        int c = t - 144; float s = 0.f;
        for (int j = 0; j < CCH; j++) s += sT[c][j] * sWq[c][j];
        sQn[c] = s;
    } else if (t < 168) {
        int c = t - 156; float s = 0.f;
        for (int j = 0; j < CCH; j++) s += sT[HD + c][j] * sWk[c][j];
        sKn[c] = s;
    }
    __syncthreads();

    if (t < HD) {
        float temp = temperature[h];
        float qn = fmaxf(sqrtf(fmaxf(sQn[t], 0.f)), 1e-12f);
        float lg[HD];
        float mx = -1e30f;
#pragma unroll
        for (int d = 0; d < HD; d++) {
            float kn = fmaxf(sqrtf(fmaxf(sKn[d], 0.f)), 1e-12f);
            lg[d] = sG[t][d] * temp / (qn * kn);
            mx = fmaxf(mx, lg[d]);
        }
        float sum = 0.f;
#pragma unroll
        for (int d = 0; d < HD; d++) { lg[d] = expf(lg[d] - mx); sum += lg[d]; }
        float inv = 1.f / sum;
#pragma unroll
        for (int d = 0; d < HD; d++) sAttn[t][d] = lg[d] * inv;
    }
    float (*sWv)[196] = sT;
    for (int i = t; i < HD * CCH; i += 192) {
        int c = i / CCH, j = i % CCH;
        sWv[c][j] = w_qkv[(2 * CCH + h * HD + c) * CCH + j];
    }
    __syncthreads();

#pragma unroll
    for (int c = 0; c < HD; c++) {
        float s = 0.f;
#pragma unroll
        for (int d = 0; d < HD; d++) s += sAttn[c][d] * sWv[d][t];
        size_t idx = (size_t)(b * CCH + h * HD + c) * CCH + t;
        unsigned short hh, ll;
        split_bf16(s, hh, ll);
        g_MHi[idx] = hh; g_MLo[idx] = ll;
    }
}

// ---------------- kernel 3b: Wproj -> bf16 hi/lo ----------------------------
__global__ void wconv_kernel(const float* __restrict__ w_proj) {
    int gid = blockIdx.x * blockDim.x + threadIdx.x;
    if (gid >= CCH * CCH) return;
    unsigned short hh, ll;
    split_bf16(w_proj[gid], hh, ll);
    g_WHi[gid] = hh; g_WLo[gid] = ll;
}

// ---------------- kernel 3c: X -> X^T bf16 hi/lo [b][p][k] -------------------
__global__ void xt_kernel(const float* __restrict__ x) {
    const int b = blockIdx.z;
    const int k0 = blockIdx.y * 32, p0 = blockIdx.x * 32;
    __shared__ float sm[32][33];
    const int tx = threadIdx.x & 31, ty = threadIdx.x >> 5;

#pragma unroll
    for (int i = 0; i < 4; i++) {
        int k = k0 + ty + i * 8;
        sm[ty + i * 8][tx] = x[((size_t)b * CCH + k) * HW + p0 + tx];
    }
    __syncthreads();
#pragma unroll
    for (int i = 0; i < 4; i++) {
        int p = p0 + ty + i * 8;
        int k = k0 + tx;
        float v = sm[tx][ty + i * 8];
        unsigned short hh, ll;
        split_bf16(v, hh, ll);
        size_t o = ((size_t)b * HW + p) * CCH + k;
        g_XThi[o] = hh;
        g_XTlo[o] = ll;
    }
}

// ---------------- kernel 4: mma.sync GEMM  C[b] = A[b] @ B[b]^T ---------------
// A:  bf16 hi/lo [192,192] row-major (aStride elems per batch; 0 = shared)
// BT: bf16 hi/lo [b][p][192]  (K contiguous)
// C:  fp32 [b][192][HW]
// Block: M=192 x N=128, 256 threads (warp grid 4m x 2n, warp tile 48x64).
// K chunks of 32, cp.async double-buffered. 3-pass split bf16.
#define SA32 20                 // smem row stride in u32 (40 bf16)
#define BUF_U32 12800           // per-buffer u32 size
#define OFF_ALO 3840
#define OFF_BHI 7680
#define OFF_BLO 10240
#define GEMM_SMEM (2 * BUF_U32 * 4)   // 102400 bytes

__global__ void __launch_bounds__(256, 1)
gemm_mma_kernel(const unsigned short* __restrict__ Ahi,
                const unsigned short* __restrict__ Alo,
                size_t aStride,
                const unsigned short* __restrict__ BThi,
                const unsigned short* __restrict__ BTlo,
                float* __restrict__ C) {
    extern __shared__ uint32_t sm32[];
    const int t = threadIdx.x;
    const int b = blockIdx.z;
    const int n0 = blockIdx.x * 128;
    const int warp = t >> 5, lane = t & 31;
    const int wm = warp & 3, wn = warp >> 2;
    const int warpM = wm * 48, warpN = wn * 64;
    const int gr = lane >> 2, qp = lane & 3;

    const unsigned short* Ah = Ahi + (size_t)b * aStride;
    const unsigned short* Al = Alo + (size_t)b * aStride;
    const unsigned short* Bh = BThi + ((size_t)b * HW + n0) * CCH;
    const unsigned short* Bl = BTlo + ((size_t)b * HW + n0) * CCH;

    const uint32_t smbase = smem_to_u32(sm32);

    float acc[3][8][4] = {};

    // ---- cp.async chunk loader ----
    auto issue_chunk = [&](int buf, int kc) {
        const uint32_t sb = smbase + buf * (BUF_U32 * 4);
        const int kb = kc * 32;
        // A: 192 rows x 4 quads (16B) per stream; 768 items, 3 per thread
#pragma unroll
        for (int i = t; i < 768; i += 256) {
            int row = i >> 2, q = i & 3;
            uint32_t dst = sb + (row * SA32 + q * 4) * 4;
            cp_async16(dst,                Ah + (size_t)row * CCH + kb + q * 8);
            cp_async16(dst + OFF_ALO * 4,  Al + (size_t)row * CCH + kb + q * 8);
        }
        // B: 128 rows x 4 quads per stream; 512 items, 2 per thread
#pragma unroll
        for (int i = t; i < 512; i += 256) {
            int row = i >> 2, q = i & 3;
            uint32_t dst = sb + (OFF_BHI + row * SA32 + q * 4) * 4;
            cp_async16(dst,                       Bh + (size_t)row * CCH + kb + q * 8);
            cp_async16(dst + (OFF_BLO - OFF_BHI) * 4, Bl + (size_t)row * CCH + kb + q * 8);
        }
        CP_COMMIT();
    };

    issue_chunk(0, 0);

    int buf = 0;
    for (int kc = 0; kc < 6; kc++) {
        if (kc < 5) {
            issue_chunk(buf ^ 1, kc + 1);
            CP_WAIT(1);
        } else {
            CP_WAIT(0);
        }
        __syncthreads();

        const uint32_t* S = sm32 + buf * BUF_U32;
#pragma unroll
        for (int ks = 0; ks < 2; ks++) {
            const int k8 = ks * 8;
            uint32_t ah[3][4], al[3][4], bh[8][2], bl[8][2];
#pragma unroll
            for (int mt = 0; mt < 3; mt++) {
                int base = (warpM + mt * 16 + gr) * SA32 + k8 + qp;
                ah[mt][0] = S[base];           ah[mt][1] = S[base + 8 * SA32];
                ah[mt][2] = S[base + 4];       ah[mt][3] = S[base + 8 * SA32 + 4];
                al[mt][0] = S[OFF_ALO + base];           al[mt][1] = S[OFF_ALO + base + 8 * SA32];
                al[mt][2] = S[OFF_ALO + base + 4];       al[mt][3] = S[OFF_ALO + base + 8 * SA32 + 4];
            }
#pragma unroll
            for (int nt = 0; nt < 8; nt++) {
                int base = (warpN + nt * 8 + gr) * SA32 + k8 + qp;
                bh[nt][0] = S[OFF_BHI + base]; bh[nt][1] = S[OFF_BHI + base + 4];
                bl[nt][0] = S[OFF_BLO + base]; bl[nt][1] = S[OFF_BLO + base + 4];
            }
#pragma unroll
            for (int mt = 0; mt < 3; mt++)
#pragma unroll
                for (int nt = 0; nt < 8; nt++) {
                    mma_bf16(acc[mt][nt], ah[mt], bh[nt]);
                    mma_bf16(acc[mt][nt], ah[mt], bl[nt]);
                    mma_bf16(acc[mt][nt], al[mt], bh[nt]);
                }
        }
        __syncthreads();
        buf ^= 1;
    }

    // ---- epilogue ----
#pragma unroll
    for (int mt = 0; mt < 3; mt++) {
        int m = warpM + mt * 16 + gr;
        float* c0 = C + ((size_t)b * CCH + m) * HW + n0 + warpN + qp * 2;
        float* c1 = C + ((size_t)b * CCH + m + 8) * HW + n0 + warpN + qp * 2;
#pragma unroll
        for (int nt = 0; nt < 8; nt++) {
            *(float2*)(c0 + nt * 8) = make_float2(acc[mt][nt][0], acc[mt][nt][1]);
            *(float2*)(c1 + nt * 8) = make_float2(acc[mt][nt][2], acc[mt][nt][3]);
        }
    }
}

// ---------------- kernel 6: depthwise 3x3 -> Z^T bf16 hi/lo [b][p][c] --------
__global__ void dwconv_t_kernel(const float* __restrict__ wdw) {
    const int b = blockIdx.z;
    const int c0 = blockIdx.y * 32;
    const int p0 = blockIdx.x * 32;
    const int y  = p0 >> 7;
    const int x0 = p0 & 127;

    __shared__ float sw[32][9];
    __shared__ float st[32][33];   // [px][chLocal]

    const int t = threadIdx.x;
    for (int idx = t; idx < 288; idx += 256)
        sw[idx / 9][idx % 9] = wdw[(c0 + idx / 9) * 9 + idx % 9];
    __syncthreads();

    const int tx = t & 31;      // px
    const int tg = t >> 5;      // 0..7
    const int xx = x0 + tx;

#pragma unroll
    for (int i = 0; i < 4; i++) {
        int chL = tg + i * 8;
        const float* Yc = g_Y + ((size_t)b * CCH + c0 + chL) * HW;
        float acc = 0.f;
#pragma unroll
        for (int ky = 0; ky < 3; ky++) {
            int sy = y + ky - 1;
            if (sy < 0 || sy >= 128) continue;
#pragma unroll
            for (int kx = 0; kx < 3; kx++) {
                int sx = xx + kx - 1;
                if (sx < 0 || sx >= 128) continue;
                acc += sw[chL][ky * 3 + kx] * __ldg(Yc + sy * 128 + sx);
            }
        }
        st[tx][chL] = acc;
    }
    __syncthreads();

    const int row = t >> 3;
    const int ch4 = (t & 7) * 4;
    float v0 = st[row][ch4 + 0], v1 = st[row][ch4 + 1];
    float v2 = st[row][ch4 + 2], v3 = st[row][ch4 + 3];
    unsigned short h0, l0, h1, l1, h2, l2, h3, l3;
    split_bf16(v0, h0, l0); split_bf16(v1, h1, l1);
    split_bf16(v2, h2, l2); split_bf16(v3, h3, l3);
    size_t o = ((size_t)b * HW + p0 + row) * CCH + c0 + ch4;
    *(uint32_t*)(g_ZThi + o)     = (uint32_t)h0 | ((uint32_t)h1 << 16);
    *(uint32_t*)(g_ZThi + o + 2) = (uint32_t)h2 | ((uint32_t)h3 << 16);
    *(uint32_t*)(g_ZTlo + o)     = (uint32_t)l0 | ((uint32_t)l1 << 16);
    *(uint32_t*)(g_ZTlo + o + 2) = (uint32_t)l2 | ((uint32_t)l3 << 16);
}

// ---------------- launch ----------------
extern "C" void kernel_launch(void* const* d_in, const int* in_sizes, int n_in,
                              void* d_out, int out_size) {
    const float* x           = (const float*)d_in[0];
    const float* w_qkv       = (const float*)d_in[1];
    const float* w_dw        = (const float*)d_in[2];
    const float* w_proj      = (const float*)d_in[3];
    const float* temperature = (const float*)d_in[4];
    float* out = (float*)d_out;

    cudaFuncSetAttribute(gemm_mma_kernel,
                         cudaFuncAttributeMaxDynamicSharedMemorySize, GEMM_SMEM);

    float* pY;
    unsigned short *pMHi, *pMLo, *pWHi, *pWLo, *pXThi, *pXTlo, *pZThi, *pZTlo;
    cudaGetSymbolAddress((void**)&pY, g_Y);
    cudaGetSymbolAddress((void**)&pMHi, g_MHi);
    cudaGetSymbolAddress((void**)&pMLo, g_MLo);
    cudaGetSymbolAddress((void**)&pWHi, g_WHi);
    cudaGetSymbolAddress((void**)&pWLo, g_WLo);
    cudaGetSymbolAddress((void**)&pXThi, g_XThi);
    cudaGetSymbolAddress((void**)&pXTlo, g_XTlo);
    cudaGetSymbolAddress((void**)&pZThi, g_ZThi);
    cudaGetSymbolAddress((void**)&pZTlo, g_ZTlo);

    // 1) S = X X^T
    s_partial_kernel<<<dim3(6, NSPLIT, BATCH), 128>>>(x);
    s_reduce_kernel<<<(BATCH * CCH * CCH + 255) / 256, 256>>>();

    // 2) attention -> Meff (bf16 hi/lo), Wproj convert, X transpose+convert
    attn_build_kernel<<<dim3(HEADS, BATCH), 192>>>(w_qkv, temperature);
    wconv_kernel<<<(CCH * CCH + 255) / 256, 256>>>(w_proj);
    xt_kernel<<<dim3(HW / 32, CCH / 32, BATCH), 256>>>(x);

    // 3) Y = Meff @ X   (mma.sync split-bf16)
    gemm_mma_kernel<<<dim3(HW / 128, 1, BATCH), 256, GEMM_SMEM>>>(
        pMHi, pMLo, (size_t)CCH * CCH, pXThi, pXTlo, pY);

    // 4) depthwise 3x3 -> Z^T bf16 hi/lo
    dwconv_t_kernel<<<dim3(HW / 32, CCH / 32, BATCH), 256>>>(w_dw);

    // 5) out = Wproj @ Z   (mma.sync split-bf16)
    gemm_mma_kernel<<<dim3(HW / 128, 1, BATCH), 256, GEMM_SMEM>>>(
        pWHi, pWLo, (size_t)0, pZThi, pZTlo, out);
}

// round 8
// speedup vs baseline: 1.9666x; 1.2403x over previous
#include <cuda_runtime.h>
#include <cuda_bf16.h>
#include <math.h>
#include <stdint.h>

#define BATCH 8
#define CCH 192
#define HEADS 16
#define HD 12
#define HW 16384
#define SSPLIT 16
#define SKCH 1024   // HW / SSPLIT

// ---------------- scratch (device globals; no allocation) ----------------
__device__ float g_Spart[BATCH * SSPLIT * CCH * CCH];
__device__ float g_S[BATCH * CCH * CCH];
__device__ float g_Y[(size_t)BATCH * CCH * HW];                 // attention output fp32
__device__ unsigned short g_MHi[BATCH * CCH * CCH];             // Meff bf16 hi
__device__ unsigned short g_MLo[BATCH * CCH * CCH];             // Meff bf16 lo
__device__ unsigned short g_WHi[CCH * CCH];                     // Wproj bf16 hi
__device__ unsigned short g_WLo[CCH * CCH];
__device__ unsigned short g_Xhi[(size_t)BATCH * CCH * HW];      // X bf16 hi [b][c][p]
__device__ unsigned short g_Xlo[(size_t)BATCH * CCH * HW];
__device__ unsigned short g_XThi[(size_t)BATCH * HW * CCH];     // X^T bf16 hi [b][p][k]
__device__ unsigned short g_XTlo[(size_t)BATCH * HW * CCH];
__device__ unsigned short g_ZThi[(size_t)BATCH * HW * CCH];     // dw(Y)^T bf16 hi [b][p][c]
__device__ unsigned short g_ZTlo[(size_t)BATCH * HW * CCH];

__constant__ int c_tm[6] = {0, 0, 0, 1, 1, 2};
__constant__ int c_tn[6] = {0, 1, 2, 1, 2, 2};

__device__ __forceinline__ void split_bf16(float v, unsigned short& h, unsigned short& l) {
    __nv_bfloat16 bh = __float2bfloat16(v);
    float hf = __bfloat162float(bh);
    __nv_bfloat16 bl = __float2bfloat16(v - hf);
    h = __bfloat16_as_ushort(bh);
    l = __bfloat16_as_ushort(bl);
}

__device__ __forceinline__ uint32_t smem_to_u32(const void* smem_ptr) {
    uint32_t addr;
    asm("{ .reg .u64 tmp; cvta.to.shared.u64 tmp, %1; cvt.u32.u64 %0, tmp; }"
        : "=r"(addr) : "l"(smem_ptr));
    return addr;
}
__device__ __forceinline__ void cp_async16(uint32_t dst, const void* src) {
    asm volatile("cp.async.cg.shared.global [%0], [%1], 16;" :: "r"(dst), "l"(src) : "memory");
}
#define CP_COMMIT() asm volatile("cp.async.commit_group;" ::: "memory")
#define CP_WAIT(n)  asm volatile("cp.async.wait_group %0;" :: "n"(n) : "memory")

__device__ __forceinline__ void mma_bf16(float* c, const uint32_t* a, const uint32_t* b) {
    asm volatile(
        "mma.sync.aligned.m16n8k16.row.col.f32.bf16.bf16.f32 "
        "{%0,%1,%2,%3}, {%4,%5,%6,%7}, {%8,%9}, {%0,%1,%2,%3};"
        : "+f"(c[0]), "+f"(c[1]), "+f"(c[2]), "+f"(c[3])
        : "r"(a[0]), "r"(a[1]), "r"(a[2]), "r"(a[3]), "r"(b[0]), "r"(b[1]));
}

// ---------------- kernel 1: S partials = X X^T via mma (split-bf16) ----------
// grid (6 upper tile-pairs, SSPLIT, BATCH), 128 threads.
// 64x64 tile, warp grid 2x2 (warp tile 32x32), K-chunk 1024, cp.async x2 buf.
#define S_SA 20      // smem row stride in u32 (32 k = 16 u32 + 4 pad)
#define S_AHI 0
#define S_ALO 1280
#define S_BHI 2560
#define S_BLO 3840
#define S_BUF 5120

__global__ void __launch_bounds__(128, 2) s_mma_kernel() {
    __shared__ uint32_t sm32[2 * S_BUF];

    const int tm = c_tm[blockIdx.x], tn = c_tn[blockIdx.x];
    const int ks = blockIdx.y, b = blockIdx.z;
    const int t = threadIdx.x;
    const int warp = t >> 5, lane = t & 31;
    const int wm = warp & 1, wn = warp >> 1;
    const int warpM = wm * 32, warpN = wn * 32;
    const int gr = lane >> 2, qp = lane & 3;

    const size_t k0 = (size_t)ks * SKCH;
    const unsigned short* Ah = g_Xhi + ((size_t)b * CCH + tm * 64) * HW + k0;
    const unsigned short* Al = g_Xlo + ((size_t)b * CCH + tm * 64) * HW + k0;
    const unsigned short* Bh = g_Xhi + ((size_t)b * CCH + tn * 64) * HW + k0;
    const unsigned short* Bl = g_Xlo + ((size_t)b * CCH + tn * 64) * HW + k0;

    const uint32_t smbase = smem_to_u32(sm32);

    float acc[2][4][4] = {};

    auto issue_chunk = [&](int buf, int kc) {
        const uint32_t sb = smbase + buf * (S_BUF * 4);
        const int kb = kc * 32;
        // 64 rows x 4 quads per stream; 256 items, 2 per thread, 4 streams
#pragma unroll
        for (int i = t; i < 256; i += 128) {
            int row = i >> 2, q = i & 3;
            uint32_t dst = sb + (row * S_SA + q * 4) * 4;
            const size_t off = (size_t)row * HW + kb + q * 8;
            cp_async16(dst + S_AHI * 4, Ah + off);
            cp_async16(dst + S_ALO * 4, Al + off);
            cp_async16(dst + S_BHI * 4, Bh + off);
            cp_async16(dst + S_BLO * 4, Bl + off);
        }
        CP_COMMIT();
    };

    issue_chunk(0, 0);

    int buf = 0;
    const int NIT = SKCH / 32;   // 32
    for (int kc = 0; kc < NIT; kc++) {
        if (kc < NIT - 1) {
            issue_chunk(buf ^ 1, kc + 1);
            CP_WAIT(1);
        } else {
            CP_WAIT(0);
        }
        __syncthreads();

        const uint32_t* S = sm32 + buf * S_BUF;
#pragma unroll
        for (int kk = 0; kk < 2; kk++) {
            const int k8 = kk * 8;
            uint32_t ah[2][4], al[2][4], bh[4][2], bl[4][2];
#pragma unroll
            for (int mt = 0; mt < 2; mt++) {
                int base = (warpM + mt * 16 + gr) * S_SA + k8 + qp;
                ah[mt][0] = S[S_AHI + base];     ah[mt][1] = S[S_AHI + base + 8 * S_SA];
                ah[mt][2] = S[S_AHI + base + 4]; ah[mt][3] = S[S_AHI + base + 8 * S_SA + 4];
                al[mt][0] = S[S_ALO + base];     al[mt][1] = S[S_ALO + base + 8 * S_SA];
                al[mt][2] = S[S_ALO + base + 4]; al[mt][3] = S[S_ALO + base + 8 * S_SA + 4];
            }
#pragma unroll
            for (int nt = 0; nt < 4; nt++) {
                int base = (warpN + nt * 8 + gr) * S_SA + k8 + qp;
                bh[nt][0] = S[S_BHI + base]; bh[nt][1] = S[S_BHI + base + 4];
                bl[nt][0] = S[S_BLO + base]; bl[nt][1] = S[S_BLO + base + 4];
            }
#pragma unroll
            for (int mt = 0; mt < 2; mt++)
#pragma unroll
                for (int nt = 0; nt < 4; nt++) {
                    mma_bf16(acc[mt][nt], ah[mt], bh[nt]);
                    mma_bf16(acc[mt][nt], ah[mt], bl[nt]);
                    mma_bf16(acc[mt][nt], al[mt], bh[nt]);
                }
        }
        __syncthreads();
        buf ^= 1;
    }

    float* sp = g_Spart + (size_t)(b * SSPLIT + ks) * CCH * CCH;
#pragma unroll
    for (int mt = 0; mt < 2; mt++) {
        int m = tm * 64 + warpM + mt * 16 + gr;
        float* r0 = sp + (size_t)m * CCH + tn * 64 + warpN + qp * 2;
        float* r1 = sp + (size_t)(m + 8) * CCH + tn * 64 + warpN + qp * 2;
#pragma unroll
        for (int nt = 0; nt < 4; nt++) {
            *(float2*)(r0 + nt * 8) = make_float2(acc[mt][nt][0], acc[mt][nt][1]);
            *(float2*)(r1 + nt * 8) = make_float2(acc[mt][nt][2], acc[mt][nt][3]);
        }
    }
}

// ---------------- kernel 2: reduce split-K partials (mirror lower) ----------
__global__ void s_reduce_kernel() {
    int gid = blockIdx.x * blockDim.x + threadIdx.x;
    if (gid >= BATCH * CCH * CCH) return;
    int b = gid / (CCH * CCH), mn = gid % (CCH * CCH);
    int m = mn / CCH, n = mn % CCH;
    int off = ((m >> 6) <= (n >> 6)) ? (m * CCH + n) : (n * CCH + m);
    const float* base = g_Spart + (size_t)b * SSPLIT * CCH * CCH;
    float s = 0.f;
#pragma unroll
    for (int ks = 0; ks < SSPLIT; ks++)
        s += base[(size_t)ks * CCH * CCH + off];
    g_S[gid] = s;
}

// ---------------- kernel 3: per-(b,h) attention -> Meff (bf16 hi/lo) --------
__global__ void attn_build_kernel(const float* __restrict__ w_qkv,
                                  const float* __restrict__ temperature) {
    const int h = blockIdx.x, b = blockIdx.y, t = threadIdx.x;

    __shared__ float sWq[HD][196];
    __shared__ float sWk[HD][196];
    __shared__ float sT[2 * HD][196];
    __shared__ float sG[HD][HD];
    __shared__ float sAttn[HD][HD];
    __shared__ float sQn[HD], sKn[HD];

    for (int i = t; i < HD * CCH; i += 192) {
        int c = i / CCH, j = i % CCH;
        sWq[c][j] = w_qkv[(h * HD + c) * CCH + j];
        sWk[c][j] = w_qkv[(CCH + h * HD + c) * CCH + j];
    }
    __syncthreads();

    {
        float tq[HD] = {}, tk[HD] = {};
        const float* Sb = g_S + b * CCH * CCH;
        for (int m = 0; m < CCH; m++) {
            float s = Sb[m * CCH + t];
#pragma unroll
            for (int c = 0; c < HD; c++) { tq[c] += sWq[c][m] * s; tk[c] += sWk[c][m] * s; }
        }
#pragma unroll
        for (int c = 0; c < HD; c++) { sT[c][t] = tq[c]; sT[HD + c][t] = tk[c]; }
    }
    __syncthreads();

    if (t < 144) {
        int c = t / HD, d = t % HD;
        float s = 0.f;
        for (int j = 0; j < CCH; j++) s += sT[c][j] * sWk[d][j];
        sG[c][d] = s;
    } else if (t < 156) {
        int c = t - 144; float s = 0.f;
        for (int j = 0; j < CCH; j++) s += sT[c][j] * sWq[c][j];
        sQn[c] = s;
    } else if (t < 168) {
        int c = t - 156; float s = 0.f;
        for (int j = 0; j < CCH; j++) s += sT[HD + c][j] * sWk[c][j];
        sKn[c] = s;
    }
    __syncthreads();

    if (t < HD) {
        float temp = temperature[h];
        float qn = fmaxf(sqrtf(fmaxf(sQn[t], 0.f)), 1e-12f);
        float lg[HD];
        float mx = -1e30f;
#pragma unroll
        for (int d = 0; d < HD; d++) {
            float kn = fmaxf(sqrtf(fmaxf(sKn[d], 0.f)), 1e-12f);
            lg[d] = sG[t][d] * temp / (qn * kn);
            mx = fmaxf(mx, lg[d]);
        }
        float sum = 0.f;
#pragma unroll
        for (int d = 0; d < HD; d++) { lg[d] = expf(lg[d] - mx); sum += lg[d]; }
        float inv = 1.f / sum;
#pragma unroll
        for (int d = 0; d < HD; d++) sAttn[t][d] = lg[d] * inv;
    }
    float (*sWv)[196] = sT;
    for (int i = t; i < HD * CCH; i += 192) {
        int c = i / CCH, j = i % CCH;
        sWv[c][j] = w_qkv[(2 * CCH + h * HD + c) * CCH + j];
    }
    __syncthreads();

#pragma unroll
    for (int c = 0; c < HD; c++) {
        float s = 0.f;
#pragma unroll
        for (int d = 0; d < HD; d++) s += sAttn[c][d] * sWv[d][t];
        size_t idx = (size_t)(b * CCH + h * HD + c) * CCH + t;
        unsigned short hh, ll;
        split_bf16(s, hh, ll);
        g_MHi[idx] = hh; g_MLo[idx] = ll;
    }
}

// ---------------- kernel 3b: Wproj -> bf16 hi/lo ----------------------------
__global__ void wconv_kernel(const float* __restrict__ w_proj) {
    int gid = blockIdx.x * blockDim.x + threadIdx.x;
    if (gid >= CCH * CCH) return;
    unsigned short hh, ll;
    split_bf16(w_proj[gid], hh, ll);
    g_WHi[gid] = hh; g_WLo[gid] = ll;
}

// ---------------- kernel 3c: X -> XT hi/lo [b][p][k]  AND X hi/lo [b][k][p] --
__global__ void xt_kernel(const float* __restrict__ x) {
    const int b = blockIdx.z;
    const int k0 = blockIdx.y * 32, p0 = blockIdx.x * 32;
    __shared__ float sm[32][33];
    const int tx = threadIdx.x & 31, ty = threadIdx.x >> 5;

#pragma unroll
    for (int i = 0; i < 4; i++) {
        int k = k0 + ty + i * 8;
        float v = x[((size_t)b * CCH + k) * HW + p0 + tx];
        sm[ty + i * 8][tx] = v;
        unsigned short hh, ll;
        split_bf16(v, hh, ll);
        size_t o = ((size_t)b * CCH + k) * HW + p0 + tx;
        g_Xhi[o] = hh;
        g_Xlo[o] = ll;
    }
    __syncthreads();
#pragma unroll
    for (int i = 0; i < 4; i++) {
        int p = p0 + ty + i * 8;
        int k = k0 + tx;
        float v = sm[tx][ty + i * 8];
        unsigned short hh, ll;
        split_bf16(v, hh, ll);
        size_t o = ((size_t)b * HW + p) * CCH + k;
        g_XThi[o] = hh;
        g_XTlo[o] = ll;
    }
}

// ---------------- kernel 4: mma.sync GEMM  C[b] = A[b] @ B[b]^T ---------------
#define SA32 20                 // smem row stride in u32 (40 bf16)
#define BUF_U32 12800           // per-buffer u32 size
#define OFF_ALO 3840
#define OFF_BHI 7680
#define OFF_BLO 10240
#define GEMM_SMEM (2 * BUF_U32 * 4)   // 102400 bytes

__global__ void __launch_bounds__(256, 1)
gemm_mma_kernel(const unsigned short* __restrict__ Ahi,
                const unsigned short* __restrict__ Alo,
                size_t aStride,
                const unsigned short* __restrict__ BThi,
                const unsigned short* __restrict__ BTlo,
                float* __restrict__ C) {
    extern __shared__ uint32_t sm32[];
    const int t = threadIdx.x;
    const int b = blockIdx.z;
    const int n0 = blockIdx.x * 128;
    const int warp = t >> 5, lane = t & 31;
    const int wm = warp & 3, wn = warp >> 2;
    const int warpM = wm * 48, warpN = wn * 64;
    const int gr = lane >> 2, qp = lane & 3;

    const unsigned short* Ah = Ahi + (size_t)b * aStride;
    const unsigned short* Al = Alo + (size_t)b * aStride;
    const unsigned short* Bh = BThi + ((size_t)b * HW + n0) * CCH;
    const unsigned short* Bl = BTlo + ((size_t)b * HW + n0) * CCH;

    const uint32_t smbase = smem_to_u32(sm32);

    float acc[3][8][4] = {};

    auto issue_chunk = [&](int buf, int kc) {
        const uint32_t sb = smbase + buf * (BUF_U32 * 4);
        const int kb = kc * 32;
#pragma unroll
        for (int i = t; i < 768; i += 256) {
            int row = i >> 2, q = i & 3;
            uint32_t dst = sb + (row * SA32 + q * 4) * 4;
            cp_async16(dst,                Ah + (size_t)row * CCH + kb + q * 8);
            cp_async16(dst + OFF_ALO * 4,  Al + (size_t)row * CCH + kb + q * 8);
        }
#pragma unroll
        for (int i = t; i < 512; i += 256) {
            int row = i >> 2, q = i & 3;
            uint32_t dst = sb + (OFF_BHI + row * SA32 + q * 4) * 4;
            cp_async16(dst,                       Bh + (size_t)row * CCH + kb + q * 8);
            cp_async16(dst + (OFF_BLO - OFF_BHI) * 4, Bl + (size_t)row * CCH + kb + q * 8);
        }
        CP_COMMIT();
    };

    issue_chunk(0, 0);

    int buf = 0;
    for (int kc = 0; kc < 6; kc++) {
        if (kc < 5) {
            issue_chunk(buf ^ 1, kc + 1);
            CP_WAIT(1);
        } else {
            CP_WAIT(0);
        }
        __syncthreads();

        const uint32_t* S = sm32 + buf * BUF_U32;
#pragma unroll
        for (int ks = 0; ks < 2; ks++) {
            const int k8 = ks * 8;
            uint32_t ah[3][4], al[3][4], bh[8][2], bl[8][2];
#pragma unroll
            for (int mt = 0; mt < 3; mt++) {
                int base = (warpM + mt * 16 + gr) * SA32 + k8 + qp;
                ah[mt][0] = S[base];           ah[mt][1] = S[base + 8 * SA32];
                ah[mt][2] = S[base + 4];       ah[mt][3] = S[base + 8 * SA32 + 4];
                al[mt][0] = S[OFF_ALO + base];           al[mt][1] = S[OFF_ALO + base + 8 * SA32];
                al[mt][2] = S[OFF_ALO + base + 4];       al[mt][3] = S[OFF_ALO + base + 8 * SA32 + 4];
            }
#pragma unroll
            for (int nt = 0; nt < 8; nt++) {
                int base = (warpN + nt * 8 + gr) * SA32 + k8 + qp;
                bh[nt][0] = S[OFF_BHI + base]; bh[nt][1] = S[OFF_BHI + base + 4];
                bl[nt][0] = S[OFF_BLO + base]; bl[nt][1] = S[OFF_BLO + base + 4];
            }
#pragma unroll
            for (int mt = 0; mt < 3; mt++)
#pragma unroll
                for (int nt = 0; nt < 8; nt++) {
                    mma_bf16(acc[mt][nt], ah[mt], bh[nt]);
                    mma_bf16(acc[mt][nt], ah[mt], bl[nt]);
                    mma_bf16(acc[mt][nt], al[mt], bh[nt]);
                }
        }
        __syncthreads();
        buf ^= 1;
    }

#pragma unroll
    for (int mt = 0; mt < 3; mt++) {
        int m = warpM + mt * 16 + gr;
        float* c0 = C + ((size_t)b * CCH + m) * HW + n0 + warpN + qp * 2;
        float* c1 = C + ((size_t)b * CCH + m + 8) * HW + n0 + warpN + qp * 2;
#pragma unroll
        for (int nt = 0; nt < 8; nt++) {
            *(float2*)(c0 + nt * 8) = make_float2(acc[mt][nt][0], acc[mt][nt][1]);
            *(float2*)(c1 + nt * 8) = make_float2(acc[mt][nt][2], acc[mt][nt][3]);
        }
    }
}

// ---------------- kernel 6: depthwise 3x3 -> Z^T bf16 hi/lo [b][p][c] --------
__global__ void dwconv_t_kernel(const float* __restrict__ wdw) {
    const int b = blockIdx.z;
    const int c0 = blockIdx.y * 32;
    const int p0 = blockIdx.x * 32;
    const int y  = p0 >> 7;
    const int x0 = p0 & 127;

    __shared__ float sw[32][9];
    __shared__ float st[32][33];   // [px][chLocal]

    const int t = threadIdx.x;
    for (int idx = t; idx < 288; idx += 256)
        sw[idx / 9][idx % 9] = wdw[(c0 + idx / 9) * 9 + idx % 9];
    __syncthreads();

    const int tx = t & 31;      // px
    const int tg = t >> 5;      // 0..7
    const int xx = x0 + tx;

#pragma unroll
    for (int i = 0; i < 4; i++) {
        int chL = tg + i * 8;
        const float* Yc = g_Y + ((size_t)b * CCH + c0 + chL) * HW;
        float acc = 0.f;
#pragma unroll
        for (int ky = 0; ky < 3; ky++) {
            int sy = y + ky - 1;
            if (sy < 0 || sy >= 128) continue;
#pragma unroll
            for (int kx = 0; kx < 3; kx++) {
                int sx = xx + kx - 1;
                if (sx < 0 || sx >= 128) continue;
                acc += sw[chL][ky * 3 + kx] * __ldg(Yc + sy * 128 + sx);
            }
        }
        st[tx][chL] = acc;
    }
    __syncthreads();

    const int row = t >> 3;
    const int ch4 = (t & 7) * 4;
    float v0 = st[row][ch4 + 0], v1 = st[row][ch4 + 1];
    float v2 = st[row][ch4 + 2], v3 = st[row][ch4 + 3];
    unsigned short h0, l0, h1, l1, h2, l2, h3, l3;
    split_bf16(v0, h0, l0); split_bf16(v1, h1, l1);
    split_bf16(v2, h2, l2); split_bf16(v3, h3, l3);
    size_t o = ((size_t)b * HW + p0 + row) * CCH + c0 + ch4;
    *(uint32_t*)(g_ZThi + o)     = (uint32_t)h0 | ((uint32_t)h1 << 16);
    *(uint32_t*)(g_ZThi + o + 2) = (uint32_t)h2 | ((uint32_t)h3 << 16);
    *(uint32_t*)(g_ZTlo + o)     = (uint32_t)l0 | ((uint32_t)l1 << 16);
    *(uint32_t*)(g_ZTlo + o + 2) = (uint32_t)l2 | ((uint32_t)l3 << 16);
}

// ---------------- launch ----------------
extern "C" void kernel_launch(void* const* d_in, const int* in_sizes, int n_in,
                              void* d_out, int out_size) {
    const float* x           = (const float*)d_in[0];
    const float* w_qkv       = (const float*)d_in[1];
    const float* w_dw        = (const float*)d_in[2];
    const float* w_proj      = (const float*)d_in[3];
    const float* temperature = (const float*)d_in[4];
    float* out = (float*)d_out;

    cudaFuncSetAttribute(gemm_mma_kernel,
                         cudaFuncAttributeMaxDynamicSharedMemorySize, GEMM_SMEM);

    float* pY;
    unsigned short *pMHi, *pMLo, *pWHi, *pWLo, *pXThi, *pXTlo, *pZThi, *pZTlo;
    cudaGetSymbolAddress((void**)&pY, g_Y);
    cudaGetSymbolAddress((void**)&pMHi, g_MHi);
    cudaGetSymbolAddress((void**)&pMLo, g_MLo);
    cudaGetSymbolAddress((void**)&pWHi, g_WHi);
    cudaGetSymbolAddress((void**)&pWLo, g_WLo);
    cudaGetSymbolAddress((void**)&pXThi, g_XThi);
    cudaGetSymbolAddress((void**)&pXTlo, g_XTlo);
    cudaGetSymbolAddress((void**)&pZThi, g_ZThi);
    cudaGetSymbolAddress((void**)&pZTlo, g_ZTlo);

    // 0) X -> bf16 hi/lo in both layouts
    xt_kernel<<<dim3(HW / 32, CCH / 32, BATCH), 256>>>(x);
    wconv_kernel<<<(CCH * CCH + 255) / 256, 256>>>(w_proj);

    // 1) S = X X^T (tensor-core split-K partials + deterministic mirror-reduce)
    s_mma_kernel<<<dim3(6, SSPLIT, BATCH), 128>>>();
    s_reduce_kernel<<<(BATCH * CCH * CCH + 255) / 256, 256>>>();

    // 2) attention -> Meff (bf16 hi/lo)
    attn_build_kernel<<<dim3(HEADS, BATCH), 192>>>(w_qkv, temperature);

    // 3) Y = Meff @ X   (mma.sync split-bf16)
    gemm_mma_kernel<<<dim3(HW / 128, 1, BATCH), 256, GEMM_SMEM>>>(
        pMHi, pMLo, (size_t)CCH * CCH, pXThi, pXTlo, pY);

    // 4) depthwise 3x3 -> Z^T bf16 hi/lo
    dwconv_t_kernel<<<dim3(HW / 32, CCH / 32, BATCH), 256>>>(w_dw);

    // 5) out = Wproj @ Z   (mma.sync split-bf16)
    gemm_mma_kernel<<<dim3(HW / 128, 1, BATCH), 256, GEMM_SMEM>>>(
        pWHi, pWLo, (size_t)0, pZThi, pZTlo, out);
}